// round 1
// baseline (speedup 1.0000x reference)
#include <cuda_runtime.h>
#include <math.h>

#define B_ 16
#define R_ 1024
#define F_ 128
#define D_ 128
#define K_ 7
#define H_ 512
#define H2_ 256
#define FEAT_ 263   // 2*D + K

// ---------------- device scratch (static, allocation-free) ----------------
__device__ float S_g[B_ * R_ * F_];        // 8 MB  masked interaction map S
__device__ float Zrow_g[B_ * R_];          // sum_f exp(S + (1-fg)*NEG)
__device__ float pscore_g[B_ * R_];        // S.sum(f) * prot_mask
__device__ float craw_g[B_ * R_];          // sum_f lcoef_f * exp(S + (1-pm)*NEG)
__device__ float Zcol_g[B_ * F_];          // sum_r exp(S + (1-pm)*NEG)
__device__ float ligraw_g[B_ * F_];        // S.sum(r)   (mask applied later)
__device__ float abarraw_g[B_ * F_];       // sum_r (pscore_r/Zrow_r) * exp(S + (1-fg)*NEG)
__device__ float lcoef_g[B_ * F_];         // ligraw*fg / Zcol
__device__ float tstr_g[B_ * 8];           // type strength [B,K], padded
__device__ float w_g[8];                   // softplus(type_weight)
__device__ float scal_g[B_ * 4];           // inv_psum, inv_lsum, sum_pw, sum_lw
__device__ float Pw_g[B_ * D_];            // sum_r pw_r * P[r,:]
__device__ float Cw_g[B_ * D_];            // sum_r c_r  * P[r,:]
__device__ float Lw_g[B_ * D_];            // sum_f lw_f * L[f,:]
__device__ float gv_g[B_ * D_];            // sum_f abar_f * L[f,:]

// ---------------- helpers ----------------
__device__ __forceinline__ float warpSum(float v) {
    #pragma unroll
    for (int o = 16; o > 0; o >>= 1) v += __shfl_down_sync(0xffffffffu, v, o);
    return v;
}

// block reduce, result broadcast to all threads. sm must hold >= 32 floats.
__device__ __forceinline__ float blockReduceSum(float v, float* sm) {
    int lane = threadIdx.x & 31, w = threadIdx.x >> 5;
    int nw = (blockDim.x + 31) >> 5;
    v = warpSum(v);
    if (lane == 0) sm[w] = v;
    __syncthreads();
    float r = (threadIdx.x < nw) ? sm[threadIdx.x] : 0.0f;
    if (w == 0) r = warpSum(r);
    if (threadIdx.x == 0) sm[0] = r;
    __syncthreads();
    r = sm[0];
    __syncthreads();   // allow safe smem reuse by caller
    return r;
}

// ---------------- K0: zero accumulators, softplus(type_weight), clear d_out ----
__global__ void k0_init(const float* __restrict__ tw, float* __restrict__ dout, int osz) {
    int tid = blockIdx.x * blockDim.x + threadIdx.x;
    int stride = gridDim.x * blockDim.x;
    if (blockIdx.x == 0 && threadIdx.x < 8) {
        float v = 0.0f;
        if (threadIdx.x < K_) {
            float x = tw[threadIdx.x];
            v = fmaxf(x, 0.0f) + log1pf(expf(-fabsf(x)));   // stable softplus
        }
        w_g[threadIdx.x] = v;
    }
    for (int i = tid; i < B_ * F_; i += stride) {
        Zcol_g[i] = 0.0f; ligraw_g[i] = 0.0f; abarraw_g[i] = 0.0f;
    }
    for (int i = tid; i < B_ * D_; i += stride) { Pw_g[i] = 0.0f; Cw_g[i] = 0.0f; }
    for (int i = tid; i < B_ * 8; i += stride) tstr_g[i] = 0.0f;
    for (int i = tid; i < osz; i += stride) dout[i] = 0.0f;
}

// ---------------- K1: logits softmax-over-K -> S, row stats, type strength ----
__global__ void k1_logits(const float* __restrict__ logits,
                          const float* __restrict__ fg_mask,
                          const float* __restrict__ prot_mask) {
    int b = blockIdx.y, r = blockIdx.x, f = threadIdx.x;
    __shared__ float wsh[8];
    __shared__ float tp[7][4];
    __shared__ float rs[4], re[4];
    if (f < 8) wsh[f] = w_g[f];
    __syncthreads();

    const float* lp = logits + ((size_t)(b * R_ + r) * F_ + f) * K_;
    float x[K_];
    #pragma unroll
    for (int k = 0; k < K_; k++) x[k] = lp[k];
    float m = x[0];
    #pragma unroll
    for (int k = 1; k < K_; k++) m = fmaxf(m, x[k]);
    float e[K_], s = 0.0f;
    #pragma unroll
    for (int k = 0; k < K_; k++) { e[k] = __expf(x[k] - m); s += e[k]; }
    float inv = 1.0f / s;
    float wk[K_], Sv = 0.0f;
    #pragma unroll
    for (int k = 0; k < K_; k++) { wk[k] = e[k] * inv * wsh[k]; Sv += wk[k]; }

    float pm = prot_mask[b * R_ + r];
    float fg = fg_mask[b * F_ + f];
    float Sm = Sv * pm * fg;
    S_g[(size_t)(b * R_ + r) * F_ + f] = Sm;

    float er = __expf(Sm - (1.0f - fg) * 1e9f);   // exp of masked row entry

    int lane = f & 31, w = f >> 5;
    float sS = warpSum(Sm);
    float sE = warpSum(er);
    if (lane == 0) { rs[w] = sS; re[w] = sE; }
    #pragma unroll
    for (int k = 0; k < K_; k++) {
        float t = warpSum(wk[k]);
        if (lane == 0) tp[k][w] = t;
    }
    __syncthreads();
    if (f == 0) {
        pscore_g[b * R_ + r] = (rs[0] + rs[1] + rs[2] + rs[3]) * pm;
        Zrow_g[b * R_ + r]   = re[0] + re[1] + re[2] + re[3];
    }
    if (f < K_) {
        atomicAdd(&tstr_g[b * 8 + f], tp[f][0] + tp[f][1] + tp[f][2] + tp[f][3]);
    }
}

// ---------------- K2: column stats over R (Zcol, ligraw, abar_raw) ----------
__global__ void k2_colstats(const float* __restrict__ fg_mask,
                            const float* __restrict__ prot_mask) {
    int b = blockIdx.y, chunk = blockIdx.x;
    int tid = threadIdx.x;
    int f = tid & 127, rh = tid >> 7;      // 256 threads: 2 r-groups x 128 f
    float fg = fg_mask[b * F_ + f];
    float mfg = (1.0f - fg) * 1e9f;
    float zc = 0.0f, sc = 0.0f, ab = 0.0f;
    int r0 = chunk * 128 + rh * 64;
    for (int i = 0; i < 64; i++) {
        int r = r0 + i;
        float pm   = prot_mask[b * R_ + r];
        float coef = pscore_g[b * R_ + r] / Zrow_g[b * R_ + r];
        float Sm   = S_g[(size_t)(b * R_ + r) * F_ + f];
        float efg = __expf(Sm - mfg);
        float epm = __expf(Sm - (1.0f - pm) * 1e9f);
        zc += epm;
        sc += Sm;
        ab += coef * efg;
    }
    atomicAdd(&Zcol_g[b * F_ + f], zc);
    atomicAdd(&ligraw_g[b * F_ + f], sc);
    atomicAdd(&abarraw_g[b * F_ + f], ab);
}

// ---------------- K3: per-batch scalar normalizers + lcoef -----------------
__global__ void k3_scalars(const float* __restrict__ fg_mask) {
    int b = blockIdx.x, tid = threadIdx.x;    // 1024 threads
    __shared__ float sm[32];
    float v = pscore_g[b * R_ + tid];
    float psum = blockReduceSum(v, sm);
    float l = 0.0f;
    if (tid < F_) l = ligraw_g[b * F_ + tid] * fg_mask[b * F_ + tid];
    float lsum = blockReduceSum(l, sm);
    if (tid < F_) lcoef_g[b * F_ + tid] = l / Zcol_g[b * F_ + tid];
    if (tid == 0) {
        float ip = 1.0f / (psum + 1e-8f);
        float il = 1.0f / (lsum + 1e-8f);
        scal_g[b * 4 + 0] = ip;
        scal_g[b * 4 + 1] = il;
        scal_g[b * 4 + 2] = psum * ip;
        scal_g[b * 4 + 3] = lsum * il;
    }
}

// ---------------- K4: c_raw[b,r] = sum_f lcoef_f * exp(S + (1-pm)*NEG) -----
__global__ void k4_crow(const float* __restrict__ prot_mask) {
    int b = blockIdx.y, r = blockIdx.x, f = threadIdx.x;
    __shared__ float rs[4];
    float pm = prot_mask[b * R_ + r];
    float Sm = S_g[(size_t)(b * R_ + r) * F_ + f];
    float e = __expf(Sm - (1.0f - pm) * 1e9f);
    float v = lcoef_g[b * F_ + f] * e;
    int lane = f & 31, w = f >> 5;
    v = warpSum(v);
    if (lane == 0) rs[w] = v;
    __syncthreads();
    if (f == 0) craw_g[b * R_ + r] = rs[0] + rs[1] + rs[2] + rs[3];
}

// ---------------- K5: weighted reductions over P and L ---------------------
__global__ void k5_pool(const float* __restrict__ protein_emb,
                        const float* __restrict__ ligand_emb,
                        const float* __restrict__ fg_mask) {
    int b = blockIdx.y, x = blockIdx.x, d = threadIdx.x;
    float ip = scal_g[b * 4 + 0], il = scal_g[b * 4 + 1];
    if (x < 8) {
        float a1 = 0.0f, a2 = 0.0f;
        int r0 = x * 128;
        for (int i = 0; i < 128; i++) {
            int r = r0 + i;
            float pc = pscore_g[b * R_ + r] * ip;
            float cc = craw_g[b * R_ + r] * il;
            float v = protein_emb[(size_t)(b * R_ + r) * D_ + d];
            a1 += pc * v;
            a2 += cc * v;
        }
        atomicAdd(&Pw_g[b * D_ + d], a1);
        atomicAdd(&Cw_g[b * D_ + d], a2);
    } else {
        float ag = 0.0f, aL = 0.0f;
        for (int f = 0; f < F_; f++) {
            float la = abarraw_g[b * F_ + f] * ip;
            float lw = ligraw_g[b * F_ + f] * fg_mask[b * F_ + f] * il;
            float v = ligand_emb[(size_t)(b * F_ + f) * D_ + d];
            ag += la * v;
            aL += lw * v;
        }
        gv_g[b * D_ + d] = ag;
        Lw_g[b * D_ + d] = aL;
    }
}

// ---------------- K6: pools -> final_feat -> norm -> MLP head --------------
__global__ void k6_head(const float* __restrict__ Wr, const float* __restrict__ br,
                        const float* __restrict__ Wf, const float* __restrict__ bf,
                        const float* __restrict__ W1, const float* __restrict__ b1,
                        const float* __restrict__ W2, const float* __restrict__ b2,
                        const float* __restrict__ W3, const float* __restrict__ b3,
                        float* __restrict__ dout, int osz) {
    int b = blockIdx.x, tid = threadIdx.x;   // 512 threads
    __shared__ float feat[FEAT_ + 1];
    __shared__ float gs[D_], cs[D_];
    __shared__ float h1[H_], h2[H2_];
    __shared__ float sm[32];

    if (tid < D_) { gs[tid] = gv_g[b * D_ + tid]; cs[tid] = Cw_g[b * D_ + tid]; }
    __syncthreads();

    float spw = scal_g[b * 4 + 2], slw = scal_g[b * 4 + 3];
    if (tid < D_) {
        float acc = 0.0f;
        const float* wrow = Wr + tid * D_;
        #pragma unroll 4
        for (int j = 0; j < D_; j++) acc += wrow[j] * gs[j];
        feat[tid] = Pw_g[b * D_ + tid] + acc + spw * br[tid];
    } else if (tid < 2 * D_) {
        int d = tid - D_;
        float acc = 0.0f;
        const float* wrow = Wf + d * D_;
        #pragma unroll 4
        for (int j = 0; j < D_; j++) acc += wrow[j] * cs[j];
        feat[tid] = Lw_g[b * D_ + d] + acc + slw * bf[d];
    } else if (tid < FEAT_) {
        feat[tid] = tstr_g[b * 8 + (tid - 2 * D_)];
    }
    __syncthreads();

    float v = (tid < FEAT_) ? feat[tid] * feat[tid] : 0.0f;
    float nrm = blockReduceSum(v, sm);
    float inv = 1.0f / fmaxf(sqrtf(nrm), 1e-12f);
    if (tid < FEAT_) {
        int oi = B_ + b * FEAT_ + tid;
        if (oi < osz) dout[oi] = feat[tid] * inv;
    }

    // MLP uses UNNORMALIZED final_feat (matches reference)
    {
        float acc = b1[tid];
        const float* wrow = W1 + tid * FEAT_;
        for (int j = 0; j < FEAT_; j++) acc += wrow[j] * feat[j];
        h1[tid] = fmaxf(acc, 0.0f);
    }
    __syncthreads();
    if (tid < H2_) {
        float acc = b2[tid];
        const float* wrow = W2 + tid * H_;
        #pragma unroll 4
        for (int j = 0; j < H_; j++) acc += wrow[j] * h1[j];
        h2[tid] = fmaxf(acc, 0.0f);
    }
    __syncthreads();
    float pv = (tid < H2_) ? W3[tid] * h2[tid] : 0.0f;
    float ps = blockReduceSum(pv, sm);
    if (tid == 0 && b < osz) dout[b] = ps + b3[0];
}

// ---------------- launch ----------------
extern "C" void kernel_launch(void* const* d_in, const int* in_sizes, int n_in,
                              void* d_out, int out_size) {
    const float* lig    = (const float*)d_in[0];
    const float* prot   = (const float*)d_in[1];
    const float* logits = (const float*)d_in[2];
    const float* fg     = (const float*)d_in[3];
    const float* pmsk   = (const float*)d_in[4];
    const float* tw     = (const float*)d_in[5];
    const float* Wr = (const float*)d_in[6];  const float* br = (const float*)d_in[7];
    const float* Wf = (const float*)d_in[8];  const float* bf = (const float*)d_in[9];
    const float* W1 = (const float*)d_in[10]; const float* b1 = (const float*)d_in[11];
    const float* W2 = (const float*)d_in[12]; const float* b2 = (const float*)d_in[13];
    const float* W3 = (const float*)d_in[14]; const float* b3 = (const float*)d_in[15];
    float* out = (float*)d_out;

    k0_init<<<32, 256>>>(tw, out, out_size);
    k1_logits<<<dim3(R_, B_), F_>>>(logits, fg, pmsk);
    k2_colstats<<<dim3(8, B_), 256>>>(fg, pmsk);
    k3_scalars<<<B_, 1024>>>(fg);
    k4_crow<<<dim3(R_, B_), F_>>>(pmsk);
    k5_pool<<<dim3(9, B_), D_>>>(prot, lig, fg);
    k6_head<<<B_, H_>>>(Wr, br, Wf, bf, W1, b1, W2, b2, W3, b3, out, out_size);
}

// round 2
// speedup vs baseline: 1.3089x; 1.3089x over previous
#include <cuda_runtime.h>
#include <math.h>

#define B_ 16
#define R_ 1024
#define F_ 128
#define D_ 128
#define K_ 7
#define H_ 512
#define H2_ 256
#define FEAT_ 263   // 2*D + K
#define TR_ 8       // rows per block in K1/K3

// ---------------- device scratch (static, allocation-free) ----------------
__device__ float S_g[B_ * R_ * F_];        // 8 MB masked interaction map S
__device__ float Zrow_g[B_ * R_];          // sum_f exp(S)*mexp_f
__device__ float pscore_g[B_ * R_];        // S.sum(f) * prot_mask
__device__ float coef_g[B_ * R_];          // pscore / Zrow
__device__ float Zcol_g[B_ * F_];          // sum_r exp(S)*mexp_r
__device__ float ligcol_g[B_ * F_];        // S.sum(r)
__device__ float abarraw_g[B_ * F_];       // sum_r coef_r * exp(S)
__device__ float lcoef_g[B_ * F_];         // ligcol*fg / Zcol
__device__ float tstr_g[B_ * 8];           // type strength [B,K]
__device__ float w_g[8];                   // softplus(type_weight)
__device__ float scal_g[B_ * 4];           // ip, il, spw, slw
__device__ float Pw_g[B_ * D_];            // sum_r pw_r * P[r,:]
__device__ float Cw_g[B_ * D_];            // sum_r c_r  * P[r,:]

// ---------------- helpers ----------------
__device__ __forceinline__ float warpSum(float v) {
    #pragma unroll
    for (int o = 16; o > 0; o >>= 1) v += __shfl_down_sync(0xffffffffu, v, o);
    return v;
}

__device__ __forceinline__ float blockReduceSum(float v, float* sm) {
    int lane = threadIdx.x & 31, w = threadIdx.x >> 5;
    int nw = (blockDim.x + 31) >> 5;
    v = warpSum(v);
    if (lane == 0) sm[w] = v;
    __syncthreads();
    float r = (threadIdx.x < nw) ? sm[threadIdx.x] : 0.0f;
    if (w == 0) r = warpSum(r);
    if (threadIdx.x == 0) sm[0] = r;
    __syncthreads();
    r = sm[0];
    __syncthreads();
    return r;
}

// ---------------- K0: zero accumulators, softplus(type_weight) -------------
__global__ void k0_init(const float* __restrict__ tw, float* __restrict__ dout, int osz) {
    int tid = blockIdx.x * blockDim.x + threadIdx.x;
    int stride = gridDim.x * blockDim.x;
    if (blockIdx.x == 0 && threadIdx.x < 8) {
        float v = 0.0f;
        if (threadIdx.x < K_) {
            float x = tw[threadIdx.x];
            v = fmaxf(x, 0.0f) + log1pf(expf(-fabsf(x)));   // stable softplus
        }
        w_g[threadIdx.x] = v;
    }
    for (int i = tid; i < B_ * F_; i += stride) {
        Zcol_g[i] = 0.0f; ligcol_g[i] = 0.0f; abarraw_g[i] = 0.0f;
    }
    for (int i = tid; i < B_ * D_; i += stride) { Pw_g[i] = 0.0f; Cw_g[i] = 0.0f; }
    for (int i = tid; i < B_ * 8; i += stride) tstr_g[i] = 0.0f;
    for (int i = tid; i < osz; i += stride) dout[i] = 0.0f;
}

// ---------------- K1: logits pass (softmax-K, S, row stats, col partials) --
__global__ void __launch_bounds__(F_) k1_logits(const float* __restrict__ logits,
                          const float* __restrict__ fg_mask,
                          const float* __restrict__ prot_mask) {
    int b = blockIdx.y, f = threadIdx.x;
    int r0 = blockIdx.x * TR_;
    int lane = f & 31, w = f >> 5;

    __shared__ float buf[F_ * K_];     // 896 floats = one logits row
    __shared__ float red[8];
    __shared__ float wsh[8];
    __shared__ float tred[K_][4];

    if (f < 8) wsh[f] = w_g[f];

    float fg  = fg_mask[b * F_ + f];
    float mexf = __expf(-(1.0f - fg) * 1e9f);

    float zc = 0.0f, lc = 0.0f;
    float tk[K_];
    #pragma unroll
    for (int k = 0; k < K_; k++) tk[k] = 0.0f;

    __syncthreads();   // wsh visible

    for (int rt = 0; rt < TR_; rt++) {
        int r = r0 + rt;
        // stage logits row: 224 float4 by 128 threads, coalesced
        const float4* src = (const float4*)logits + (size_t)(b * R_ + r) * 224;
        float4* b4 = (float4*)buf;
        b4[f] = src[f];
        if (f < 96) b4[128 + f] = src[128 + f];
        __syncthreads();

        float x[K_];
        #pragma unroll
        for (int k = 0; k < K_; k++) x[k] = buf[f * K_ + k];   // stride 7: conflict-free
        float m = x[0];
        #pragma unroll
        for (int k = 1; k < K_; k++) m = fmaxf(m, x[k]);
        float e[K_], s = 0.0f;
        #pragma unroll
        for (int k = 0; k < K_; k++) { e[k] = __expf(x[k] - m); s += e[k]; }
        float inv = __fdividef(1.0f, s);
        float Sv = 0.0f;
        #pragma unroll
        for (int k = 0; k < K_; k++) { float wk = e[k] * inv * wsh[k]; tk[k] += wk; Sv += wk; }

        float pm = prot_mask[b * R_ + r];            // broadcast
        float Sm = Sv * pm * fg;
        S_g[(size_t)(b * R_ + r) * F_ + f] = Sm;
        float E = __expf(Sm);

        float sS = warpSum(Sm);
        float sE = warpSum(E * mexf);
        if (lane == 0) { red[w] = sS; red[4 + w] = sE; }
        __syncthreads();
        if (f == 0) {
            float ps = red[0] + red[1] + red[2] + red[3];
            pscore_g[b * R_ + r] = ps * pm;
            Zrow_g[b * R_ + r]   = red[4] + red[5] + red[6] + red[7];
        }
        float mexr = __expf(-(1.0f - pm) * 1e9f);
        zc += E * mexr;
        lc += Sm;
        // next iteration's buf write is safe: all buf reads completed before the
        // sync above; red rewrite is after the next iteration's sync.
    }

    atomicAdd(&Zcol_g[b * F_ + f], zc);
    atomicAdd(&ligcol_g[b * F_ + f], lc);

    #pragma unroll
    for (int k = 0; k < K_; k++) {
        float t = warpSum(tk[k]);
        if (lane == 0) tred[k][w] = t;
    }
    __syncthreads();
    if (f < K_)
        atomicAdd(&tstr_g[b * 8 + f], tred[f][0] + tred[f][1] + tred[f][2] + tred[f][3]);
}

// ---------------- K2: per-batch scalars, coef, lcoef -----------------------
__global__ void k2_scalars(const float* __restrict__ fg_mask) {
    int b = blockIdx.x, tid = threadIdx.x;    // 1024 threads
    __shared__ float sm[32];
    float ps = pscore_g[b * R_ + tid];
    float zr = Zrow_g[b * R_ + tid];
    float psum = blockReduceSum(ps, sm);
    coef_g[b * R_ + tid] = __fdividef(ps, zr);
    float l = 0.0f;
    if (tid < F_) l = ligcol_g[b * F_ + tid] * fg_mask[b * F_ + tid];
    float lsum = blockReduceSum(l, sm);
    if (tid < F_) lcoef_g[b * F_ + tid] = __fdividef(l, Zcol_g[b * F_ + tid]);
    if (tid == 0) {
        float ip = __fdividef(1.0f, psum + 1e-8f);
        float il = __fdividef(1.0f, lsum + 1e-8f);
        scal_g[b * 4 + 0] = ip;
        scal_g[b * 4 + 1] = il;
        scal_g[b * 4 + 2] = psum * ip;
        scal_g[b * 4 + 3] = lsum * il;
    }
}

// ---------------- K3: S pass (craw, abar) fused with protein pooling -------
__global__ void __launch_bounds__(F_) k3_spass(const float* __restrict__ protein_emb,
                         const float* __restrict__ prot_mask) {
    int b = blockIdx.y, f = threadIdx.x;
    int r0 = blockIdx.x * TR_;
    int lane = f & 31, w = f >> 5;

    __shared__ float red[2][4];

    float lco = lcoef_g[b * F_ + f];
    float ip = scal_g[b * 4 + 0], il = scal_g[b * 4 + 1];

    float Pacc = 0.0f, Cacc = 0.0f, ab = 0.0f;

    for (int rt = 0; rt < TR_; rt++) {
        int r = r0 + rt;
        int p = rt & 1;
        float Sm = S_g[(size_t)(b * R_ + r) * F_ + f];
        float E = __expf(Sm);
        float pm = prot_mask[b * R_ + r];
        float mexr = __expf(-(1.0f - pm) * 1e9f);

        float sv = warpSum(lco * E);
        if (lane == 0) red[p][w] = sv;
        __syncthreads();
        float craw = mexr * (red[p][0] + red[p][1] + red[p][2] + red[p][3]);

        float coefr = coef_g[b * R_ + r];
        ab += coefr * E;

        float Pv = protein_emb[(size_t)(b * R_ + r) * D_ + f];
        float pw = pscore_g[b * R_ + r] * ip;
        Pacc += pw * Pv;
        Cacc += (craw * il) * Pv;
    }

    atomicAdd(&Pw_g[b * D_ + f], Pacc);
    atomicAdd(&Cw_g[b * D_ + f], Cacc);
    atomicAdd(&abarraw_g[b * F_ + f], ab);
}

// ---------------- K5: ligand pooling + feat + norm + MLP head --------------
__global__ void __launch_bounds__(H_) k5_head(const float* __restrict__ ligand_emb,
                        const float* __restrict__ fg_mask,
                        const float* __restrict__ Wr, const float* __restrict__ br,
                        const float* __restrict__ Wf, const float* __restrict__ bf,
                        const float* __restrict__ W1, const float* __restrict__ b1,
                        const float* __restrict__ W2, const float* __restrict__ b2,
                        const float* __restrict__ W3, const float* __restrict__ b3,
                        float* __restrict__ dout, int osz) {
    int b = blockIdx.x, tid = threadIdx.x;   // 512 threads
    int chunk = tid >> 7, d = tid & 127;

    __shared__ float gpart[4][D_], lpart[4][D_];
    __shared__ float gs[D_], cs[D_], Ls[D_];
    __shared__ float feat[FEAT_ + 1];
    __shared__ float h1[H_], h2[H2_];
    __shared__ float sm[32];

    float ip = scal_g[b * 4 + 0], il = scal_g[b * 4 + 1];

    // ligand pooling: 4 f-chunks x 128 d
    float ag = 0.0f, aL = 0.0f;
    for (int i = 0; i < 32; i++) {
        int f = chunk * 32 + i;
        float fg = fg_mask[b * F_ + f];
        float mexf = __expf(-(1.0f - fg) * 1e9f);
        float la = abarraw_g[b * F_ + f] * mexf * ip;
        float lw = ligcol_g[b * F_ + f] * fg * il;
        float v = ligand_emb[(size_t)(b * F_ + f) * D_ + d];
        ag += la * v;
        aL += lw * v;
    }
    gpart[chunk][d] = ag;
    lpart[chunk][d] = aL;
    __syncthreads();
    if (tid < D_) {
        gs[tid] = gpart[0][tid] + gpart[1][tid] + gpart[2][tid] + gpart[3][tid];
        Ls[tid] = lpart[0][tid] + lpart[1][tid] + lpart[2][tid] + lpart[3][tid];
        cs[tid] = Cw_g[b * D_ + tid];
    }
    __syncthreads();

    float spw = scal_g[b * 4 + 2], slw = scal_g[b * 4 + 3];
    if (tid < D_) {
        float acc = 0.0f;
        const float* wrow = Wr + tid * D_;
        #pragma unroll 4
        for (int j = 0; j < D_; j++) acc += wrow[j] * gs[j];
        feat[tid] = Pw_g[b * D_ + tid] + acc + spw * br[tid];
    } else if (tid < 2 * D_) {
        int dd = tid - D_;
        float acc = 0.0f;
        const float* wrow = Wf + dd * D_;
        #pragma unroll 4
        for (int j = 0; j < D_; j++) acc += wrow[j] * cs[j];
        feat[tid] = Ls[dd] + acc + slw * bf[dd];
    } else if (tid < FEAT_) {
        feat[tid] = tstr_g[b * 8 + (tid - 2 * D_)];
    }
    __syncthreads();

    float v = (tid < FEAT_) ? feat[tid] * feat[tid] : 0.0f;
    float nrm = blockReduceSum(v, sm);
    float inv = 1.0f / fmaxf(sqrtf(nrm), 1e-12f);
    if (tid < FEAT_) {
        int oi = B_ + b * FEAT_ + tid;
        if (oi < osz) dout[oi] = feat[tid] * inv;
    }

    // MLP on UNNORMALIZED final_feat (matches reference)
    {
        float acc = b1[tid];
        const float* wrow = W1 + tid * FEAT_;
        for (int j = 0; j < FEAT_; j++) acc += wrow[j] * feat[j];
        h1[tid] = fmaxf(acc, 0.0f);
    }
    __syncthreads();
    if (tid < H2_) {
        float acc = b2[tid];
        const float* wrow = W2 + tid * H_;
        #pragma unroll 4
        for (int j = 0; j < H_; j++) acc += wrow[j] * h1[j];
        h2[tid] = fmaxf(acc, 0.0f);
    }
    __syncthreads();
    float pv = (tid < H2_) ? W3[tid] * h2[tid] : 0.0f;
    float ps = blockReduceSum(pv, sm);
    if (tid == 0 && b < osz) dout[b] = ps + b3[0];
}

// ---------------- launch ----------------
extern "C" void kernel_launch(void* const* d_in, const int* in_sizes, int n_in,
                              void* d_out, int out_size) {
    const float* lig    = (const float*)d_in[0];
    const float* prot   = (const float*)d_in[1];
    const float* logits = (const float*)d_in[2];
    const float* fg     = (const float*)d_in[3];
    const float* pmsk   = (const float*)d_in[4];
    const float* tw     = (const float*)d_in[5];
    const float* Wr = (const float*)d_in[6];  const float* br = (const float*)d_in[7];
    const float* Wf = (const float*)d_in[8];  const float* bf = (const float*)d_in[9];
    const float* W1 = (const float*)d_in[10]; const float* b1 = (const float*)d_in[11];
    const float* W2 = (const float*)d_in[12]; const float* b2 = (const float*)d_in[13];
    const float* W3 = (const float*)d_in[14]; const float* b3 = (const float*)d_in[15];
    float* out = (float*)d_out;

    k0_init<<<32, 256>>>(tw, out, out_size);
    k1_logits<<<dim3(R_ / TR_, B_), F_>>>(logits, fg, pmsk);
    k2_scalars<<<B_, 1024>>>(fg);
    k3_spass<<<dim3(R_ / TR_, B_), F_>>>(prot, pmsk);
    k5_head<<<B_, H_>>>(lig, fg, Wr, br, Wf, bf, W1, b1, W2, b2, W3, b3, out, out_size);
}

// round 3
// speedup vs baseline: 2.8257x; 2.1589x over previous
#include <cuda_runtime.h>
#include <math.h>

#define B_ 16
#define R_ 1024
#define F_ 128
#define D_ 128
#define K_ 7
#define H_ 512
#define H2_ 256
#define FEAT_ 263   // 2*D + K
#define NB1_ 64     // k1 blocks per batch (16 rows each)
#define NB3_ 32     // k3 blocks per batch (32 rows each)

// ---------------- device scratch (static, allocation-free) ----------------
__device__ float S_g[B_ * R_ * F_];          // masked interaction map S
__device__ float Zrow_g[B_ * R_];            // sum_f exp(S)*mexf
__device__ float pscore_g[B_ * R_];          // S.sum(f) * pm
__device__ float Zcolp_g[B_ * NB1_ * F_];    // partial: sum_r exp(S)*mexr
__device__ float ligcolp_g[B_ * NB1_ * F_];  // partial: sum_r S
__device__ float tstrp_g[B_ * NB1_ * 8];     // partial type strength
__device__ float Pwp_g[B_ * NB3_ * D_];      // partial protein pool
__device__ float Cwp_g[B_ * NB3_ * D_];      // partial C pool
__device__ float abarp_g[B_ * NB3_ * F_];    // partial abar

// ---------------- helpers ----------------
__device__ __forceinline__ float warpSum(float v) {
    #pragma unroll
    for (int o = 16; o > 0; o >>= 1) v += __shfl_down_sync(0xffffffffu, v, o);
    return v;
}
__device__ __forceinline__ float warpAllSum(float v) {
    #pragma unroll
    for (int o = 16; o > 0; o >>= 1) v += __shfl_xor_sync(0xffffffffu, v, o);
    return v;
}
__device__ __forceinline__ float blockReduceSum(float v, float* sm) {
    int lane = threadIdx.x & 31, w = threadIdx.x >> 5;
    int nw = (blockDim.x + 31) >> 5;
    v = warpSum(v);
    if (lane == 0) sm[w] = v;
    __syncthreads();
    float r = (threadIdx.x < nw) ? sm[threadIdx.x] : 0.0f;
    if (w == 0) r = warpSum(r);
    if (threadIdx.x == 0) sm[0] = r;
    __syncthreads();
    r = sm[0];
    __syncthreads();
    return r;
}

// ============ K1: logits pass — warp-per-row, partial-slot outputs =========
__global__ void __launch_bounds__(256) k1_logits(const float* __restrict__ logits,
                          const float* __restrict__ fg_mask,
                          const float* __restrict__ prot_mask,
                          const float* __restrict__ tw) {
    int b = blockIdx.y, blk = blockIdx.x;
    int tid = threadIdx.x, w = tid >> 5, t = tid & 31;

    __shared__ float4 buf4[1792];          // 8 rows x 224 float4 = 28KB
    __shared__ float wsh[8];
    __shared__ float tks[8][8];

    if (tid < K_) {
        float x = tw[tid];
        wsh[tid] = fmaxf(x, 0.0f) + log1pf(expf(-fabsf(x)));
    }
    float4 fg4 = ((const float4*)(fg_mask + b * F_))[t];
    float mexf0 = __expf(-(1.0f - fg4.x) * 1e9f);
    float mexf1 = __expf(-(1.0f - fg4.y) * 1e9f);
    float mexf2 = __expf(-(1.0f - fg4.z) * 1e9f);
    float mexf3 = __expf(-(1.0f - fg4.w) * 1e9f);

    float zc0=0.f,zc1=0.f,zc2=0.f,zc3=0.f;
    float lc0=0.f,lc1=0.f,lc2=0.f,lc3=0.f;
    float tk[K_];
    #pragma unroll
    for (int k = 0; k < K_; k++) tk[k] = 0.0f;

    int r0 = blk * 16;
    #pragma unroll
    for (int tile = 0; tile < 2; tile++) {
        const float4* src = (const float4*)(logits + (size_t)(b * R_ + r0 + tile * 8) * (F_ * K_));
        __syncthreads();
        #pragma unroll
        for (int i = 0; i < 7; i++) buf4[tid + 256 * i] = src[tid + 256 * i];
        __syncthreads();

        int r = r0 + tile * 8 + w;
        float pm = prot_mask[b * R_ + r];
        float mexr = __expf(-(1.0f - pm) * 1e9f);

        float xx[28];
        #pragma unroll
        for (int u = 0; u < 7; u++) {
            float4 v = buf4[w * 224 + t * 7 + u];   // conflict-free LDS.128
            xx[u*4+0] = v.x; xx[u*4+1] = v.y; xx[u*4+2] = v.z; xx[u*4+3] = v.w;
        }
        float Sm[4], E[4];
        float fgv[4] = {fg4.x, fg4.y, fg4.z, fg4.w};
        #pragma unroll
        for (int j = 0; j < 4; j++) {
            float m = xx[j*7];
            #pragma unroll
            for (int k = 1; k < 7; k++) m = fmaxf(m, xx[j*7+k]);
            float e[7], s = 0.0f;
            #pragma unroll
            for (int k = 0; k < 7; k++) { e[k] = __expf(xx[j*7+k] - m); s += e[k]; }
            float inv = __fdividef(1.0f, s);
            float Sv = 0.0f;
            #pragma unroll
            for (int k = 0; k < 7; k++) { float wk = e[k] * inv * wsh[k]; tk[k] += wk; Sv += wk; }
            Sm[j] = Sv * pm * fgv[j];
            E[j] = __expf(Sm[j]);
        }
        ((float4*)S_g)[(size_t)(b * R_ + r) * 32 + t] = make_float4(Sm[0], Sm[1], Sm[2], Sm[3]);

        float rowS = Sm[0] + Sm[1] + Sm[2] + Sm[3];
        float rowE = E[0]*mexf0 + E[1]*mexf1 + E[2]*mexf2 + E[3]*mexf3;
        rowS = warpSum(rowS);
        rowE = warpSum(rowE);
        if (t == 0) { pscore_g[b * R_ + r] = rowS * pm; Zrow_g[b * R_ + r] = rowE; }

        zc0 += E[0]*mexr; zc1 += E[1]*mexr; zc2 += E[2]*mexr; zc3 += E[3]*mexr;
        lc0 += Sm[0]; lc1 += Sm[1]; lc2 += Sm[2]; lc3 += Sm[3];
    }

    // block-level partial reductions (deterministic slots, no atomics)
    #pragma unroll
    for (int k = 0; k < K_; k++) { float v = warpSum(tk[k]); if (t == 0) tks[w][k] = v; }
    __syncthreads();
    buf4[w * 32 + t]       = make_float4(zc0, zc1, zc2, zc3);
    buf4[256 + w * 32 + t] = make_float4(lc0, lc1, lc2, lc3);
    __syncthreads();
    if (tid < 32) {
        float4 s = buf4[tid];
        #pragma unroll
        for (int ww = 1; ww < 8; ww++) { float4 v = buf4[ww*32 + tid]; s.x += v.x; s.y += v.y; s.z += v.z; s.w += v.w; }
        ((float4*)Zcolp_g)[(size_t)(b * NB1_ + blk) * 32 + tid] = s;
    } else if (tid < 64) {
        int tt = tid - 32;
        float4 s = buf4[256 + tt];
        #pragma unroll
        for (int ww = 1; ww < 8; ww++) { float4 v = buf4[256 + ww*32 + tt]; s.x += v.x; s.y += v.y; s.z += v.z; s.w += v.w; }
        ((float4*)ligcolp_g)[(size_t)(b * NB1_ + blk) * 32 + tt] = s;
    } else if (tid < 64 + K_) {
        int k = tid - 64;
        float s = 0.0f;
        #pragma unroll
        for (int ww = 0; ww < 8; ww++) s += tks[ww][k];
        tstrp_g[(size_t)(b * NB1_ + blk) * 8 + k] = s;
    }
}

// ============ K3: S pass — warp-per-row, fused protein pooling =============
__global__ void __launch_bounds__(256) k3_spass(const float* __restrict__ protein_emb,
                        const float* __restrict__ fg_mask,
                        const float* __restrict__ prot_mask) {
    int b = blockIdx.y, blk = blockIdx.x;
    int tid = threadIdx.x, w = tid >> 5, t = tid & 31;

    __shared__ float zsm[2][128], lsm[2][128], lco_sm[128];
    __shared__ float red[32];
    __shared__ float4 rbuf[256];

    // per-batch scalars (redundant per block, L2-hot)
    float v = 0.0f;
    #pragma unroll
    for (int i = 0; i < 4; i++) v += pscore_g[b * R_ + tid + i * 256];
    float psum = blockReduceSum(v, red);
    float ip = __fdividef(1.0f, psum + 1e-8f);

    int f = tid & 127, half = tid >> 7;
    float zs = 0.0f, ls = 0.0f;
    for (int s = half * 32; s < half * 32 + 32; s++) {
        zs += Zcolp_g[(size_t)(b * NB1_ + s) * F_ + f];
        ls += ligcolp_g[(size_t)(b * NB1_ + s) * F_ + f];
    }
    zsm[half][f] = zs; lsm[half][f] = ls;
    __syncthreads();
    float lw0 = 0.0f;
    if (tid < 128) {
        float Zc = zsm[0][tid] + zsm[1][tid];
        float lg = lsm[0][tid] + lsm[1][tid];
        lw0 = lg * fg_mask[b * F_ + tid];
        lco_sm[tid] = __fdividef(lw0, Zc);
    }
    float lsum = blockReduceSum(lw0, red);
    float il = __fdividef(1.0f, lsum + 1e-8f);
    float4 lco4 = ((float4*)lco_sm)[t];

    float Pa0=0.f,Pa1=0.f,Pa2=0.f,Pa3=0.f;
    float Ca0=0.f,Ca1=0.f,Ca2=0.f,Ca3=0.f;
    float ab0=0.f,ab1=0.f,ab2=0.f,ab3=0.f;

    int rbase = blk * 32 + w * 4;
    #pragma unroll
    for (int i = 0; i < 4; i++) {
        int r = rbase + i;
        float ps = pscore_g[b * R_ + r];
        float zr = Zrow_g[b * R_ + r];
        float pm = prot_mask[b * R_ + r];
        float coefr = __fdividef(ps, zr);
        float mexr = __expf(-(1.0f - pm) * 1e9f);
        float4 S4 = ((const float4*)S_g)[(size_t)(b * R_ + r) * 32 + t];
        float E0 = __expf(S4.x), E1 = __expf(S4.y), E2 = __expf(S4.z), E3 = __expf(S4.w);
        float dv = lco4.x*E0 + lco4.y*E1 + lco4.z*E2 + lco4.w*E3;
        float cil = mexr * warpAllSum(dv) * il;
        float4 P4 = ((const float4*)protein_emb)[(size_t)(b * R_ + r) * 32 + t];
        float pw = ps * ip;
        Pa0 += pw*P4.x; Pa1 += pw*P4.y; Pa2 += pw*P4.z; Pa3 += pw*P4.w;
        Ca0 += cil*P4.x; Ca1 += cil*P4.y; Ca2 += cil*P4.z; Ca3 += cil*P4.w;
        ab0 += coefr*E0; ab1 += coefr*E1; ab2 += coefr*E2; ab3 += coefr*E3;
    }

    __syncthreads();
    rbuf[w * 32 + t] = make_float4(Pa0, Pa1, Pa2, Pa3);
    __syncthreads();
    if (tid < 32) {
        float4 s = rbuf[tid];
        #pragma unroll
        for (int ww = 1; ww < 8; ww++) { float4 vv = rbuf[ww*32 + tid]; s.x+=vv.x; s.y+=vv.y; s.z+=vv.z; s.w+=vv.w; }
        ((float4*)Pwp_g)[(size_t)(b * NB3_ + blk) * 32 + tid] = s;
    }
    __syncthreads();
    rbuf[w * 32 + t] = make_float4(Ca0, Ca1, Ca2, Ca3);
    __syncthreads();
    if (tid < 32) {
        float4 s = rbuf[tid];
        #pragma unroll
        for (int ww = 1; ww < 8; ww++) { float4 vv = rbuf[ww*32 + tid]; s.x+=vv.x; s.y+=vv.y; s.z+=vv.z; s.w+=vv.w; }
        ((float4*)Cwp_g)[(size_t)(b * NB3_ + blk) * 32 + tid] = s;
    }
    __syncthreads();
    rbuf[w * 32 + t] = make_float4(ab0, ab1, ab2, ab3);
    __syncthreads();
    if (tid < 32) {
        float4 s = rbuf[tid];
        #pragma unroll
        for (int ww = 1; ww < 8; ww++) { float4 vv = rbuf[ww*32 + tid]; s.x+=vv.x; s.y+=vv.y; s.z+=vv.z; s.w+=vv.w; }
        ((float4*)abarp_g)[(size_t)(b * NB3_ + blk) * 32 + tid] = s;
    }
}

// ============ K5: slot sums + ligand pooling + feat + MLP head =============
__global__ void __launch_bounds__(512) k5_head(const float* __restrict__ ligand_emb,
                        const float* __restrict__ fg_mask,
                        const float* __restrict__ Wr, const float* __restrict__ br,
                        const float* __restrict__ Wf, const float* __restrict__ bf,
                        const float* __restrict__ W1, const float* __restrict__ b1,
                        const float* __restrict__ W2, const float* __restrict__ b2,
                        const float* __restrict__ W3, const float* __restrict__ b3,
                        float* __restrict__ dout, int osz) {
    int b = blockIdx.x, tid = threadIdx.x, w = tid >> 5, lane = tid & 31;
    int f = tid & 127, q = tid >> 7;

    __shared__ float red[32];
    __shared__ float part[4][128];
    __shared__ float lgc[128], absum[128], Pws[128], Cws[128];
    __shared__ float la[128], lw[128];
    __shared__ float gs[128], Ls[128];
    __shared__ float feat[FEAT_ + 1];
    __shared__ float h1[H_], h2[H2_];
    __shared__ float tst[8];

    // tail-zero guard (block 0)
    if (b == 0) for (int i = B_ + B_ * FEAT_ + tid; i < osz; i += 512) dout[i] = 0.0f;

    // psum
    float v = pscore_g[b * R_ + tid] + pscore_g[b * R_ + 512 + tid];
    float psum = blockReduceSum(v, red);
    float ip = __fdividef(1.0f, psum + 1e-8f);
    float spw = psum * ip;

    // slot sums: ligcol (64), abar (32), Pw (32), Cw (32)
    float a = 0.0f;
    for (int s = q * 16; s < q * 16 + 16; s++) a += ligcolp_g[(size_t)(b * NB1_ + s) * F_ + f];
    part[q][f] = a; __syncthreads();
    if (tid < 128) lgc[tid] = part[0][tid] + part[1][tid] + part[2][tid] + part[3][tid];
    __syncthreads();
    a = 0.0f;
    for (int s = q * 8; s < q * 8 + 8; s++) a += abarp_g[(size_t)(b * NB3_ + s) * F_ + f];
    part[q][f] = a; __syncthreads();
    if (tid < 128) absum[tid] = part[0][tid] + part[1][tid] + part[2][tid] + part[3][tid];
    __syncthreads();
    a = 0.0f;
    for (int s = q * 8; s < q * 8 + 8; s++) a += Pwp_g[(size_t)(b * NB3_ + s) * D_ + f];
    part[q][f] = a; __syncthreads();
    if (tid < 128) Pws[tid] = part[0][tid] + part[1][tid] + part[2][tid] + part[3][tid];
    __syncthreads();
    a = 0.0f;
    for (int s = q * 8; s < q * 8 + 8; s++) a += Cwp_g[(size_t)(b * NB3_ + s) * D_ + f];
    part[q][f] = a; __syncthreads();
    if (tid < 128) Cws[tid] = part[0][tid] + part[1][tid] + part[2][tid] + part[3][tid];

    // type strength
    if (tid < 8) tst[tid] = 0.0f;
    __syncthreads();
    if (tid < 64 * K_) {
        int s = tid / K_, k = tid - s * K_;
        atomicAdd(&tst[k], tstrp_g[(size_t)(b * NB1_ + s) * 8 + k]);
    }

    // lsum + la/lw
    float lw0 = 0.0f;
    if (tid < 128) lw0 = lgc[tid] * fg_mask[b * F_ + tid];
    float lsum = blockReduceSum(lw0, red);
    float il = __fdividef(1.0f, lsum + 1e-8f);
    float slw = lsum * il;
    if (tid < 128) {
        float fg = fg_mask[b * F_ + tid];
        float mexf = __expf(-(1.0f - fg) * 1e9f);
        la[tid] = absum[tid] * mexf * ip;
        lw[tid] = lw0 * il;
    }
    __syncthreads();

    // ligand pooling: 4 f-chunks x 128 d
    float ag = 0.0f, aL = 0.0f;
    for (int i = 0; i < 32; i++) {
        int ff = q * 32 + i;
        float lv = ligand_emb[(size_t)(b * F_ + ff) * D_ + f];
        ag += la[ff] * lv;
        aL += lw[ff] * lv;
    }
    part[q][f] = ag; __syncthreads();
    if (tid < 128) gs[tid] = part[0][tid] + part[1][tid] + part[2][tid] + part[3][tid];
    __syncthreads();
    part[q][f] = aL; __syncthreads();
    if (tid < 128) Ls[tid] = part[0][tid] + part[1][tid] + part[2][tid] + part[3][tid];
    __syncthreads();

    // feat rows via warp-per-row (coalesced weight reads)
    #pragma unroll 1
    for (int i = 0; i < 16; i++) {
        int row = w * 16 + i;
        if (row < 128) {
            const float* Wrow = Wr + row * D_;
            float p = 0.0f;
            #pragma unroll
            for (int u = 0; u < 4; u++) p += Wrow[lane + 32*u] * gs[lane + 32*u];
            p = warpSum(p);
            if (lane == 0) feat[row] = Pws[row] + p + spw * br[row];
        } else {
            int rr = row - 128;
            const float* Wrow = Wf + rr * D_;
            float p = 0.0f;
            #pragma unroll
            for (int u = 0; u < 4; u++) p += Wrow[lane + 32*u] * Cws[lane + 32*u];
            p = warpSum(p);
            if (lane == 0) feat[row] = Ls[rr] + p + slw * bf[rr];
        }
    }
    if (tid < K_) feat[2 * D_ + tid] = tst[tid];
    __syncthreads();

    // norm + normalized-feat output
    float sv = (tid < FEAT_) ? feat[tid] * feat[tid] : 0.0f;
    float nrm = blockReduceSum(sv, red);
    float inv = 1.0f / fmaxf(sqrtf(nrm), 1e-12f);
    if (tid < FEAT_) {
        int oi = B_ + b * FEAT_ + tid;
        if (oi < osz) dout[oi] = feat[tid] * inv;
    }

    // MLP on UNNORMALIZED feat (matches reference)
    #pragma unroll 1
    for (int i = 0; i < 32; i++) {
        int h = w * 32 + i;
        const float* Wrow = W1 + h * FEAT_;
        float p = 0.0f;
        #pragma unroll
        for (int u = 0; u < 9; u++) {
            int j = lane + 32 * u;
            if (j < FEAT_) p += Wrow[j] * feat[j];
        }
        p = warpSum(p);
        if (lane == 0) h1[h] = fmaxf(p + b1[h], 0.0f);
    }
    __syncthreads();
    #pragma unroll 1
    for (int i = 0; i < 16; i++) {
        int h = w * 16 + i;
        const float* Wrow = W2 + h * H_;
        float p = 0.0f;
        #pragma unroll
        for (int u = 0; u < 16; u++) p += Wrow[lane + 32*u] * h1[lane + 32*u];
        p = warpSum(p);
        if (lane == 0) h2[h] = fmaxf(p + b2[h], 0.0f);
    }
    __syncthreads();
    float pv = (tid < H2_) ? W3[tid] * h2[tid] : 0.0f;
    float pred = blockReduceSum(pv, red);
    if (tid == 0 && b < osz) dout[b] = pred + b3[0];
}

// ---------------- launch ----------------
extern "C" void kernel_launch(void* const* d_in, const int* in_sizes, int n_in,
                              void* d_out, int out_size) {
    const float* lig    = (const float*)d_in[0];
    const float* prot   = (const float*)d_in[1];
    const float* logits = (const float*)d_in[2];
    const float* fg     = (const float*)d_in[3];
    const float* pmsk   = (const float*)d_in[4];
    const float* tw     = (const float*)d_in[5];
    const float* Wr = (const float*)d_in[6];  const float* br = (const float*)d_in[7];
    const float* Wf = (const float*)d_in[8];  const float* bf = (const float*)d_in[9];
    const float* W1 = (const float*)d_in[10]; const float* b1 = (const float*)d_in[11];
    const float* W2 = (const float*)d_in[12]; const float* b2 = (const float*)d_in[13];
    const float* W3 = (const float*)d_in[14]; const float* b3 = (const float*)d_in[15];
    float* out = (float*)d_out;

    k1_logits<<<dim3(NB1_, B_), 256>>>(logits, fg, pmsk, tw);
    k3_spass<<<dim3(NB3_, B_), 256>>>(prot, fg, pmsk);
    k5_head<<<B_, 512>>>(lig, fg, Wr, br, Wf, bf, W1, b1, W2, b2, W3, b3, out, out_size);
}

// round 4
// speedup vs baseline: 3.7263x; 1.3187x over previous
#include <cuda_runtime.h>
#include <math.h>

#define B_ 16
#define R_ 1024
#define F_ 128
#define D_ 128
#define K_ 7
#define H_ 512
#define H2_ 256
#define FEAT_ 263   // 2*D + K
#define NB1_ 32     // k1 blocks per batch (32 rows each)
#define NB3_ 16     // k35 blocks per batch (64 rows each)

// ---------------- device scratch (static, allocation-free) ----------------
__device__ float S_g[B_ * R_ * F_];          // masked interaction map S
__device__ float Zrow_g[B_ * R_];            // sum_f exp(S)*mexf
__device__ float pscore_g[B_ * R_];          // S.sum(f) * pm
__device__ float Zcolp_g[B_ * NB1_ * F_];    // partial: sum_r exp(S)*mexr
__device__ float ligcolp_g[B_ * NB1_ * F_];  // partial: sum_r S
__device__ float tstrp_g[B_ * NB1_ * 8];     // partial type strength
__device__ float Pwp_g[B_ * NB3_ * D_];      // partial protein pool
__device__ float Cwp_g[B_ * NB3_ * D_];      // partial C pool
__device__ float abarp_g[B_ * NB3_ * F_];    // partial abar
__device__ unsigned int cnt_g[B_];           // last-block counters (self-resetting)

// ---------------- helpers ----------------
__device__ __forceinline__ float warpSum(float v) {
    #pragma unroll
    for (int o = 16; o > 0; o >>= 1) v += __shfl_down_sync(0xffffffffu, v, o);
    return v;
}
__device__ __forceinline__ float warpAllSum(float v) {
    #pragma unroll
    for (int o = 16; o > 0; o >>= 1) v += __shfl_xor_sync(0xffffffffu, v, o);
    return v;
}
__device__ __forceinline__ float blockReduceSum(float v, float* sm) {
    int lane = threadIdx.x & 31, w = threadIdx.x >> 5;
    int nw = (blockDim.x + 31) >> 5;
    v = warpSum(v);
    if (lane == 0) sm[w] = v;
    __syncthreads();
    float r = (threadIdx.x < nw) ? sm[threadIdx.x] : 0.0f;
    if (w == 0) r = warpSum(r);
    if (threadIdx.x == 0) sm[0] = r;
    __syncthreads();
    r = sm[0];
    __syncthreads();
    return r;
}

// ============ K1: logits pass — warp-per-row, per-f scalar pipeline ========
__global__ void __launch_bounds__(256, 4) k1_logits(const float* __restrict__ logits,
                          const float* __restrict__ fg_mask,
                          const float* __restrict__ prot_mask,
                          const float* __restrict__ tw) {
    int b = blockIdx.y, blk = blockIdx.x;
    int tid = threadIdx.x, w = tid >> 5, t = tid & 31;

    __shared__ float buf[8 * 896];     // 28KB: 8 logits rows
    __shared__ float tks[8][8];
    __shared__ float wsh_s[8];

    if (tid < K_) {
        float x = tw[tid];
        wsh_s[tid] = fmaxf(x, 0.0f) + log1pf(expf(-fabsf(x)));
    }
    __syncthreads();
    float wshr[K_];
    #pragma unroll
    for (int k = 0; k < K_; k++) wshr[k] = wsh_s[k];

    float fgc[4], mexfc[4];
    #pragma unroll
    for (int c = 0; c < 4; c++) {
        fgc[c] = fg_mask[b * F_ + t + 32 * c];
        mexfc[c] = __expf(-(1.0f - fgc[c]) * 1e9f);
    }

    float zc[4] = {0,0,0,0}, lc[4] = {0,0,0,0};
    float tk[K_];
    #pragma unroll
    for (int k = 0; k < K_; k++) tk[k] = 0.0f;

    int r0 = blk * 32;
    for (int tile = 0; tile < 4; tile++) {
        const float4* src = (const float4*)(logits + (size_t)(b * R_ + r0 + tile * 8) * 896);
        __syncthreads();
        #pragma unroll
        for (int i = 0; i < 7; i++) ((float4*)buf)[tid + 256 * i] = src[tid + 256 * i];
        __syncthreads();

        int r = r0 + tile * 8 + w;
        float pm = prot_mask[b * R_ + r];
        float mexr = __expf(-(1.0f - pm) * 1e9f);
        float rowS = 0.0f, rowE = 0.0f;

        #pragma unroll
        for (int c = 0; c < 4; c++) {
            int fb = w * 896 + (t + 32 * c) * 7;     // lane stride 7: conflict-free
            float x0 = buf[fb+0], x1 = buf[fb+1], x2 = buf[fb+2], x3 = buf[fb+3];
            float x4 = buf[fb+4], x5 = buf[fb+5], x6 = buf[fb+6];
            float m = fmaxf(fmaxf(fmaxf(x0,x1),fmaxf(x2,x3)),fmaxf(fmaxf(x4,x5),x6));
            float e0=__expf(x0-m), e1=__expf(x1-m), e2=__expf(x2-m), e3=__expf(x3-m);
            float e4=__expf(x4-m), e5=__expf(x5-m), e6=__expf(x6-m);
            float s = e0+e1+e2+e3+e4+e5+e6;
            float inv = __fdividef(1.0f, s);
            float w0=e0*inv*wshr[0], w1=e1*inv*wshr[1], w2=e2*inv*wshr[2], w3=e3*inv*wshr[3];
            float w4=e4*inv*wshr[4], w5=e5*inv*wshr[5], w6=e6*inv*wshr[6];
            tk[0]+=w0; tk[1]+=w1; tk[2]+=w2; tk[3]+=w3; tk[4]+=w4; tk[5]+=w5; tk[6]+=w6;
            float Sv = w0+w1+w2+w3+w4+w5+w6;
            float Sm = Sv * pm * fgc[c];
            S_g[(size_t)(b * R_ + r) * F_ + t + 32 * c] = Sm;
            float E = __expf(Sm);
            rowS += Sm; rowE += E * mexfc[c];
            zc[c] += E * mexr; lc[c] += Sm;
        }
        rowS = warpSum(rowS);
        rowE = warpSum(rowE);
        if (t == 0) { pscore_g[b * R_ + r] = rowS * pm; Zrow_g[b * R_ + r] = rowE; }
    }

    // block-level partial reductions (deterministic, no atomics)
    #pragma unroll
    for (int k = 0; k < K_; k++) { float v = warpSum(tk[k]); if (t == 0) tks[w][k] = v; }
    __syncthreads();   // also guards buf reuse
    #pragma unroll
    for (int c = 0; c < 4; c++) {
        buf[w * 128 + t + 32 * c] = zc[c];
        buf[1024 + w * 128 + t + 32 * c] = lc[c];
    }
    __syncthreads();
    if (tid < 128) {
        float s = 0.0f, s2 = 0.0f;
        #pragma unroll
        for (int ww = 0; ww < 8; ww++) { s += buf[ww * 128 + tid]; s2 += buf[1024 + ww * 128 + tid]; }
        Zcolp_g[(size_t)(b * NB1_ + blk) * F_ + tid] = s;
        ligcolp_g[(size_t)(b * NB1_ + blk) * F_ + tid] = s2;
    } else if (tid < 128 + K_) {
        int k = tid - 128;
        float s = 0.0f;
        #pragma unroll
        for (int ww = 0; ww < 8; ww++) s += tks[ww][k];
        tstrp_g[(size_t)(b * NB1_ + blk) * 8 + k] = s;
    }
}

// ============ K35: S pass + protein pooling, last block runs full head =====
__global__ void __launch_bounds__(512, 2) k35(const float* __restrict__ protein_emb,
                        const float* __restrict__ ligand_emb,
                        const float* __restrict__ fg_mask,
                        const float* __restrict__ prot_mask,
                        const float* __restrict__ Wr, const float* __restrict__ br,
                        const float* __restrict__ Wf, const float* __restrict__ bf,
                        const float* __restrict__ W1, const float* __restrict__ b1,
                        const float* __restrict__ W2, const float* __restrict__ b2,
                        const float* __restrict__ W3, const float* __restrict__ b3,
                        float* __restrict__ dout, int osz) {
    int b = blockIdx.y, blk = blockIdx.x;
    int tid = threadIdx.x, w = tid >> 5, t = tid & 31;
    int f = tid & 127, q = tid >> 7;

    __shared__ float red[32];
    __shared__ float part[4][128];
    __shared__ float rbuf[16 * 128];
    __shared__ float lco_sm[128], lw_sm[128];
    __shared__ float absum[128], Pws[128], Cws[128];
    __shared__ float la_s[128], gs[128], Ls[128];
    __shared__ float feat[FEAT_ + 1];
    __shared__ float h1[H_], h2[H2_];
    __shared__ float tst[8];
    __shared__ unsigned int lastsh;

    // ---- per-batch scalars ----
    float v = pscore_g[b * R_ + tid] + pscore_g[b * R_ + 512 + tid];
    float psum = blockReduceSum(v, red);
    float ip = __fdividef(1.0f, psum + 1e-8f);

    // column stats from k1 partials (32 slots, q sums 8 each)
    float zs = 0.0f, ls = 0.0f;
    for (int s = q * 8; s < q * 8 + 8; s++) {
        zs += Zcolp_g[(size_t)(b * NB1_ + s) * F_ + f];
        ls += ligcolp_g[(size_t)(b * NB1_ + s) * F_ + f];
    }
    part[q][f] = zs;
    __syncthreads();
    float Zc = (tid < 128) ? (part[0][tid] + part[1][tid] + part[2][tid] + part[3][tid]) : 0.0f;
    __syncthreads();
    part[q][f] = ls;
    __syncthreads();
    float lw0 = 0.0f;
    if (tid < 128) {
        float lgc = part[0][tid] + part[1][tid] + part[2][tid] + part[3][tid];
        lw0 = lgc * fg_mask[b * F_ + tid];
        lco_sm[tid] = __fdividef(lw0, Zc);
    }
    float lsum = blockReduceSum(lw0, red);
    float il = __fdividef(1.0f, lsum + 1e-8f);
    if (tid < 128) lw_sm[tid] = lw0 * il;

    float lcoc[4];
    #pragma unroll
    for (int c = 0; c < 4; c++) lcoc[c] = lco_sm[t + 32 * c];

    // ---- row loop: 16 warps x 4 rows ----
    float Pa[4] = {0,0,0,0}, Ca[4] = {0,0,0,0}, ab[4] = {0,0,0,0};
    int rbase = blk * 64 + w * 4;
    #pragma unroll
    for (int i = 0; i < 4; i++) {
        int r = rbase + i;
        float ps = pscore_g[b * R_ + r];
        float zr = Zrow_g[b * R_ + r];
        float pm = prot_mask[b * R_ + r];
        float coefr = __fdividef(ps, zr);
        float mexr = __expf(-(1.0f - pm) * 1e9f);
        float E[4], dv = 0.0f;
        #pragma unroll
        for (int c = 0; c < 4; c++) {
            float Sm = S_g[(size_t)(b * R_ + r) * F_ + t + 32 * c];
            E[c] = __expf(Sm);
            dv += lcoc[c] * E[c];
        }
        float cil = mexr * warpAllSum(dv) * il;
        float pw = ps * ip;
        #pragma unroll
        for (int c = 0; c < 4; c++) {
            float Pv = protein_emb[(size_t)(b * R_ + r) * D_ + t + 32 * c];
            Pa[c] += pw * Pv;
            Ca[c] += cil * Pv;
            ab[c] += coefr * E[c];
        }
    }

    // block-reduce partials into deterministic slots
    __syncthreads();
    #pragma unroll
    for (int c = 0; c < 4; c++) rbuf[w * 128 + t + 32 * c] = Pa[c];
    __syncthreads();
    if (tid < 128) {
        float s = 0.0f;
        #pragma unroll
        for (int ww = 0; ww < 16; ww++) s += rbuf[ww * 128 + tid];
        Pwp_g[(size_t)(b * NB3_ + blk) * D_ + tid] = s;
    }
    __syncthreads();
    #pragma unroll
    for (int c = 0; c < 4; c++) rbuf[w * 128 + t + 32 * c] = Ca[c];
    __syncthreads();
    if (tid < 128) {
        float s = 0.0f;
        #pragma unroll
        for (int ww = 0; ww < 16; ww++) s += rbuf[ww * 128 + tid];
        Cwp_g[(size_t)(b * NB3_ + blk) * D_ + tid] = s;
    }
    __syncthreads();
    #pragma unroll
    for (int c = 0; c < 4; c++) rbuf[w * 128 + t + 32 * c] = ab[c];
    __syncthreads();
    if (tid < 128) {
        float s = 0.0f;
        #pragma unroll
        for (int ww = 0; ww < 16; ww++) s += rbuf[ww * 128 + tid];
        abarp_g[(size_t)(b * NB3_ + blk) * F_ + tid] = s;
    }

    // ---- last-block election ----
    __threadfence();
    if (tid == 0) lastsh = atomicInc(&cnt_g[b], NB3_ - 1);
    __syncthreads();
    if (lastsh != NB3_ - 1) return;
    __threadfence();

    // =============== HEAD (one block per batch) ===============
    if (b == 0) for (int i = B_ + B_ * FEAT_ + tid; i < osz; i += 512) dout[i] = 0.0f;

    float spw = psum * ip, slw = lsum * il;

    // slot sums (16 slots, q sums 4 each)
    float a = 0.0f;
    for (int s = q * 4; s < q * 4 + 4; s++) a += abarp_g[(size_t)(b * NB3_ + s) * F_ + f];
    part[q][f] = a; __syncthreads();
    if (tid < 128) absum[tid] = part[0][tid] + part[1][tid] + part[2][tid] + part[3][tid];
    __syncthreads();
    a = 0.0f;
    for (int s = q * 4; s < q * 4 + 4; s++) a += Pwp_g[(size_t)(b * NB3_ + s) * D_ + f];
    part[q][f] = a; __syncthreads();
    if (tid < 128) Pws[tid] = part[0][tid] + part[1][tid] + part[2][tid] + part[3][tid];
    __syncthreads();
    a = 0.0f;
    for (int s = q * 4; s < q * 4 + 4; s++) a += Cwp_g[(size_t)(b * NB3_ + s) * D_ + f];
    part[q][f] = a; __syncthreads();
    if (tid < 128) Cws[tid] = part[0][tid] + part[1][tid] + part[2][tid] + part[3][tid];

    // type strength (deterministic serial per k)
    if (tid < K_) {
        float s = 0.0f;
        for (int s2 = 0; s2 < NB1_; s2++) s += tstrp_g[(size_t)(b * NB1_ + s2) * 8 + tid];
        tst[tid] = s;
    }
    if (tid < 128) {
        float fg = fg_mask[b * F_ + tid];
        float mexf = __expf(-(1.0f - fg) * 1e9f);
        la_s[tid] = absum[tid] * mexf * ip;
    }
    __syncthreads();

    // ligand pooling: 4 f-chunks x 128 d
    float ag = 0.0f, aL = 0.0f;
    for (int i = 0; i < 32; i++) {
        int ff = q * 32 + i;
        float lv = ligand_emb[(size_t)(b * F_ + ff) * D_ + f];
        ag += la_s[ff] * lv;
        aL += lw_sm[ff] * lv;
    }
    part[q][f] = ag; __syncthreads();
    if (tid < 128) gs[tid] = part[0][tid] + part[1][tid] + part[2][tid] + part[3][tid];
    __syncthreads();
    part[q][f] = aL; __syncthreads();
    if (tid < 128) Ls[tid] = part[0][tid] + part[1][tid] + part[2][tid] + part[3][tid];
    __syncthreads();

    // feat rows: warp-per-row
    #pragma unroll 1
    for (int i = 0; i < 16; i++) {
        int row = w * 16 + i;
        if (row < 128) {
            const float* Wrow = Wr + row * D_;
            float p = 0.0f;
            #pragma unroll
            for (int u = 0; u < 4; u++) p += Wrow[t + 32*u] * gs[t + 32*u];
            p = warpSum(p);
            if (t == 0) feat[row] = Pws[row] + p + spw * br[row];
        } else {
            int rr = row - 128;
            const float* Wrow = Wf + rr * D_;
            float p = 0.0f;
            #pragma unroll
            for (int u = 0; u < 4; u++) p += Wrow[t + 32*u] * Cws[t + 32*u];
            p = warpSum(p);
            if (t == 0) feat[row] = Ls[rr] + p + slw * bf[rr];
        }
    }
    if (tid < K_) feat[2 * D_ + tid] = tst[tid];
    __syncthreads();

    // norm + normalized-feat output
    float sv = (tid < FEAT_) ? feat[tid] * feat[tid] : 0.0f;
    float nrm = blockReduceSum(sv, red);
    float inv = 1.0f / fmaxf(sqrtf(nrm), 1e-12f);
    if (tid < FEAT_) {
        int oi = B_ + b * FEAT_ + tid;
        if (oi < osz) dout[oi] = feat[tid] * inv;
    }

    // MLP on UNNORMALIZED feat
    #pragma unroll 1
    for (int i = 0; i < 32; i++) {
        int h = w * 32 + i;
        const float* Wrow = W1 + h * FEAT_;
        float p = 0.0f;
        #pragma unroll
        for (int u = 0; u < 9; u++) {
            int j = t + 32 * u;
            if (j < FEAT_) p += Wrow[j] * feat[j];
        }
        p = warpSum(p);
        if (t == 0) h1[h] = fmaxf(p + b1[h], 0.0f);
    }
    __syncthreads();
    #pragma unroll 1
    for (int i = 0; i < 16; i++) {
        int h = w * 16 + i;
        const float* Wrow = W2 + h * H_;
        float p = 0.0f;
        #pragma unroll
        for (int u = 0; u < 16; u++) p += Wrow[t + 32*u] * h1[t + 32*u];
        p = warpSum(p);
        if (t == 0) h2[h] = fmaxf(p + b2[h], 0.0f);
    }
    __syncthreads();
    float pv = (tid < H2_) ? W3[tid] * h2[tid] : 0.0f;
    float pred = blockReduceSum(pv, red);
    if (tid == 0 && b < osz) dout[b] = pred + b3[0];
}

// ---------------- launch ----------------
extern "C" void kernel_launch(void* const* d_in, const int* in_sizes, int n_in,
                              void* d_out, int out_size) {
    const float* lig    = (const float*)d_in[0];
    const float* prot   = (const float*)d_in[1];
    const float* logits = (const float*)d_in[2];
    const float* fg     = (const float*)d_in[3];
    const float* pmsk   = (const float*)d_in[4];
    const float* tw     = (const float*)d_in[5];
    const float* Wr = (const float*)d_in[6];  const float* br = (const float*)d_in[7];
    const float* Wf = (const float*)d_in[8];  const float* bf = (const float*)d_in[9];
    const float* W1 = (const float*)d_in[10]; const float* b1 = (const float*)d_in[11];
    const float* W2 = (const float*)d_in[12]; const float* b2 = (const float*)d_in[13];
    const float* W3 = (const float*)d_in[14]; const float* b3 = (const float*)d_in[15];
    float* out = (float*)d_out;

    k1_logits<<<dim3(NB1_, B_), 256>>>(logits, fg, pmsk, tw);
    k35<<<dim3(NB3_, B_), 512>>>(prot, lig, fg, pmsk, Wr, br, Wf, bf,
                                 W1, b1, W2, b2, W3, b3, out, out_size);
}

// round 5
// speedup vs baseline: 3.9769x; 1.0673x over previous
#include <cuda_runtime.h>
#include <math.h>

#define B_ 16
#define R_ 1024
#define F_ 128
#define D_ 128
#define K_ 7
#define H_ 512
#define H2_ 256
#define FEAT_ 263   // 2*D + K
#define NB1_ 32     // k1 blocks per batch (32 rows each)
#define NB3_ 16     // k35 blocks per batch (64 rows each)

// ---------------- device scratch (static, allocation-free) ----------------
__device__ float S_g[B_ * R_ * F_];          // masked interaction map S
__device__ float Zrow_g[B_ * R_];            // sum_f exp(S)*mexf
__device__ float pscore_g[B_ * R_];          // S.sum(f) * pm
__device__ float Zcolp_g[B_ * NB1_ * F_];    // partial: sum_r exp(S)*mexr
__device__ float ligcolp_g[B_ * NB1_ * F_];  // partial: sum_r S
__device__ float tstrp_g[B_ * NB1_ * 8];     // partial type strength
__device__ float Pwp_g[B_ * NB3_ * D_];      // partial protein pool
__device__ float Cwp_g[B_ * NB3_ * D_];      // partial C pool
__device__ float abarp_g[B_ * NB3_ * F_];    // partial abar
__device__ unsigned int cnt_g[B_];           // last-block counters (self-resetting)

// ---------------- helpers ----------------
__device__ __forceinline__ float warpSum(float v) {
    #pragma unroll
    for (int o = 16; o > 0; o >>= 1) v += __shfl_down_sync(0xffffffffu, v, o);
    return v;
}
__device__ __forceinline__ float warpAllSum(float v) {
    #pragma unroll
    for (int o = 16; o > 0; o >>= 1) v += __shfl_xor_sync(0xffffffffu, v, o);
    return v;
}
__device__ __forceinline__ float blockReduceSum(float v, float* sm) {
    int lane = threadIdx.x & 31, w = threadIdx.x >> 5;
    int nw = (blockDim.x + 31) >> 5;
    v = warpSum(v);
    if (lane == 0) sm[w] = v;
    __syncthreads();
    float r = (threadIdx.x < nw) ? sm[threadIdx.x] : 0.0f;
    if (w == 0) r = warpSum(r);
    if (threadIdx.x == 0) sm[0] = r;
    __syncthreads();
    r = sm[0];
    __syncthreads();
    return r;
}
__device__ __forceinline__ void l2pf(const void* p) {
    asm volatile("prefetch.global.L2 [%0];" :: "l"(p));
}

// ============ K1: logits pass — warp-per-row, per-f scalar pipeline ========
__global__ void __launch_bounds__(256, 4) k1_logits(const float* __restrict__ logits,
                          const float* __restrict__ fg_mask,
                          const float* __restrict__ prot_mask,
                          const float* __restrict__ tw) {
    int b = blockIdx.y, blk = blockIdx.x;
    int tid = threadIdx.x, w = tid >> 5, t = tid & 31;

    __shared__ float buf[8 * 896];     // 28KB: 8 logits rows
    __shared__ float tks[8][8];
    __shared__ float wsh_s[8];

    if (tid < K_) {
        float x = tw[tid];
        wsh_s[tid] = fmaxf(x, 0.0f) + log1pf(expf(-fabsf(x)));
    }
    __syncthreads();
    float wshr[K_];
    #pragma unroll
    for (int k = 0; k < K_; k++) wshr[k] = wsh_s[k];

    float fgc[4], mexfc[4];
    #pragma unroll
    for (int c = 0; c < 4; c++) {
        fgc[c] = fg_mask[b * F_ + t + 32 * c];
        mexfc[c] = __expf(-(1.0f - fgc[c]) * 1e9f);
    }

    float zc[4] = {0,0,0,0}, lc[4] = {0,0,0,0};
    float tk[K_];
    #pragma unroll
    for (int k = 0; k < K_; k++) tk[k] = 0.0f;

    int r0 = blk * 32;
    for (int tile = 0; tile < 4; tile++) {
        const float4* src = (const float4*)(logits + (size_t)(b * R_ + r0 + tile * 8) * 896);
        __syncthreads();
        #pragma unroll
        for (int i = 0; i < 7; i++) ((float4*)buf)[tid + 256 * i] = src[tid + 256 * i];
        __syncthreads();

        int r = r0 + tile * 8 + w;
        float pm = prot_mask[b * R_ + r];
        float mexr = __expf(-(1.0f - pm) * 1e9f);
        float rowS = 0.0f, rowE = 0.0f;

        #pragma unroll
        for (int c = 0; c < 4; c++) {
            int fb = w * 896 + (t + 32 * c) * 7;     // lane stride 7: conflict-free
            float x0 = buf[fb+0], x1 = buf[fb+1], x2 = buf[fb+2], x3 = buf[fb+3];
            float x4 = buf[fb+4], x5 = buf[fb+5], x6 = buf[fb+6];
            float m = fmaxf(fmaxf(fmaxf(x0,x1),fmaxf(x2,x3)),fmaxf(fmaxf(x4,x5),x6));
            float e0=__expf(x0-m), e1=__expf(x1-m), e2=__expf(x2-m), e3=__expf(x3-m);
            float e4=__expf(x4-m), e5=__expf(x5-m), e6=__expf(x6-m);
            float s = e0+e1+e2+e3+e4+e5+e6;
            float inv = __fdividef(1.0f, s);
            float w0=e0*inv*wshr[0], w1=e1*inv*wshr[1], w2=e2*inv*wshr[2], w3=e3*inv*wshr[3];
            float w4=e4*inv*wshr[4], w5=e5*inv*wshr[5], w6=e6*inv*wshr[6];
            tk[0]+=w0; tk[1]+=w1; tk[2]+=w2; tk[3]+=w3; tk[4]+=w4; tk[5]+=w5; tk[6]+=w6;
            float Sv = w0+w1+w2+w3+w4+w5+w6;
            float Sm = Sv * pm * fgc[c];
            S_g[(size_t)(b * R_ + r) * F_ + t + 32 * c] = Sm;
            float E = __expf(Sm);
            rowS += Sm; rowE += E * mexfc[c];
            zc[c] += E * mexr; lc[c] += Sm;
        }
        rowS = warpSum(rowS);
        rowE = warpSum(rowE);
        if (t == 0) { pscore_g[b * R_ + r] = rowS * pm; Zrow_g[b * R_ + r] = rowE; }
    }

    #pragma unroll
    for (int k = 0; k < K_; k++) { float v = warpSum(tk[k]); if (t == 0) tks[w][k] = v; }
    __syncthreads();
    #pragma unroll
    for (int c = 0; c < 4; c++) {
        buf[w * 128 + t + 32 * c] = zc[c];
        buf[1024 + w * 128 + t + 32 * c] = lc[c];
    }
    __syncthreads();
    if (tid < 128) {
        float s = 0.0f, s2 = 0.0f;
        #pragma unroll
        for (int ww = 0; ww < 8; ww++) { s += buf[ww * 128 + tid]; s2 += buf[1024 + ww * 128 + tid]; }
        Zcolp_g[(size_t)(b * NB1_ + blk) * F_ + tid] = s;
        ligcolp_g[(size_t)(b * NB1_ + blk) * F_ + tid] = s2;
    } else if (tid < 128 + K_) {
        int k = tid - 128;
        float s = 0.0f;
        #pragma unroll
        for (int ww = 0; ww < 8; ww++) s += tks[ww][k];
        tstrp_g[(size_t)(b * NB1_ + blk) * 8 + k] = s;
    }
}

// ============ K35: S pass + protein pooling; last block runs full head =====
__global__ void __launch_bounds__(512, 2) k35(const float* __restrict__ protein_emb,
                        const float* __restrict__ ligand_emb,
                        const float* __restrict__ fg_mask,
                        const float* __restrict__ prot_mask,
                        const float* __restrict__ Wr, const float* __restrict__ br,
                        const float* __restrict__ Wf, const float* __restrict__ bf,
                        const float* __restrict__ W1, const float* __restrict__ b1,
                        const float* __restrict__ W2, const float* __restrict__ b2,
                        const float* __restrict__ W3, const float* __restrict__ b3,
                        float* __restrict__ dout, int osz) {
    int b = blockIdx.y, blk = blockIdx.x;
    int tid = threadIdx.x, w = tid >> 5, t = tid & 31;
    int f = tid & 127, q = tid >> 7;

    __shared__ float red[32];
    __shared__ float big[6144];               // 24KB multipurpose
    __shared__ float lco_sm[128], lw_sm[128];
    __shared__ float absum[128], Pws[128], Cws[128];
    __shared__ float la_s[128], gs[128], Ls[128];
    __shared__ float feat[FEAT_ + 1];
    __shared__ float h1[H_], h2[H2_];
    __shared__ float tst[8];
    __shared__ unsigned int lastsh;

    // ---- L2 prefetch of head weights (and this batch's ligand slice) ----
    {
        int gb = b * NB3_ + blk;                       // 0..255
        long gid = (long)gb * 512 + tid;               // 0..131071
        const long n1 = 4208;                          // W1: 512*263*4/128
        const long n2 = 4096;                          // W2: 256*512*4/128
        const long nr = 512;                           // Wr/Wf each
        if (gid < n1)                 l2pf((const char*)W1 + gid * 128);
        else if (gid < n1+n2)         l2pf((const char*)W2 + (gid-n1) * 128);
        else if (gid < n1+n2+nr)      l2pf((const char*)Wr + (gid-n1-n2) * 128);
        else if (gid < n1+n2+2*nr)    l2pf((const char*)Wf + (gid-n1-n2-nr) * 128);
        if (blk == 0)                 l2pf((const char*)ligand_emb + (size_t)b * 65536 + tid * 128);
    }

    // ---- per-batch scalars ----
    float v = pscore_g[b * R_ + tid] + pscore_g[b * R_ + 512 + tid];
    float psum = blockReduceSum(v, red);
    float ip = __fdividef(1.0f, psum + 1e-8f);

    // column stats from k1 partials (32 slots, q sums 8 each)
    float zs = 0.0f, ls = 0.0f;
    for (int s = q * 8; s < q * 8 + 8; s++) {
        zs += Zcolp_g[(size_t)(b * NB1_ + s) * F_ + f];
        ls += ligcolp_g[(size_t)(b * NB1_ + s) * F_ + f];
    }
    big[q * 128 + f] = zs;
    big[512 + q * 128 + f] = ls;
    __syncthreads();
    float lw0 = 0.0f;
    if (tid < 128) {
        float Zc  = big[tid] + big[128 + tid] + big[256 + tid] + big[384 + tid];
        float lgc = big[512 + tid] + big[640 + tid] + big[768 + tid] + big[896 + tid];
        lw0 = lgc * fg_mask[b * F_ + tid];
        lco_sm[tid] = __fdividef(lw0, Zc);
    }
    float lsum = blockReduceSum(lw0, red);
    float il = __fdividef(1.0f, lsum + 1e-8f);
    if (tid < 128) lw_sm[tid] = lw0 * il;

    float lcoc[4];
    #pragma unroll
    for (int c = 0; c < 4; c++) lcoc[c] = lco_sm[t + 32 * c];

    // ---- row loop: 16 warps x 4 rows ----
    float Pa[4] = {0,0,0,0}, Ca[4] = {0,0,0,0}, ab[4] = {0,0,0,0};
    int rbase = blk * 64 + w * 4;
    #pragma unroll
    for (int i = 0; i < 4; i++) {
        int r = rbase + i;
        float ps = pscore_g[b * R_ + r];
        float zr = Zrow_g[b * R_ + r];
        float pm = prot_mask[b * R_ + r];
        float coefr = __fdividef(ps, zr);
        float mexr = __expf(-(1.0f - pm) * 1e9f);
        float E[4], dv = 0.0f;
        #pragma unroll
        for (int c = 0; c < 4; c++) {
            float Sm = S_g[(size_t)(b * R_ + r) * F_ + t + 32 * c];
            E[c] = __expf(Sm);
            dv += lcoc[c] * E[c];
        }
        float cil = mexr * warpAllSum(dv) * il;
        float pw = ps * ip;
        #pragma unroll
        for (int c = 0; c < 4; c++) {
            float Pv = protein_emb[(size_t)(b * R_ + r) * D_ + t + 32 * c];
            Pa[c] += pw * Pv;
            Ca[c] += cil * Pv;
            ab[c] += coefr * E[c];
        }
    }

    // single-stage block reduce of all three partial sets
    __syncthreads();
    #pragma unroll
    for (int c = 0; c < 4; c++) {
        big[w * 128 + t + 32 * c]        = Pa[c];
        big[2048 + w * 128 + t + 32 * c] = Ca[c];
        big[4096 + w * 128 + t + 32 * c] = ab[c];
    }
    __syncthreads();
    if (tid < 128) {
        float sP = 0.0f, sC = 0.0f, sA = 0.0f;
        #pragma unroll
        for (int ww = 0; ww < 16; ww++) {
            sP += big[ww * 128 + tid];
            sC += big[2048 + ww * 128 + tid];
            sA += big[4096 + ww * 128 + tid];
        }
        Pwp_g[(size_t)(b * NB3_ + blk) * D_ + tid] = sP;
        Cwp_g[(size_t)(b * NB3_ + blk) * D_ + tid] = sC;
        abarp_g[(size_t)(b * NB3_ + blk) * F_ + tid] = sA;
    }

    // ---- last-block election ----
    __threadfence();
    if (tid == 0) lastsh = atomicInc(&cnt_g[b], NB3_ - 1);
    __syncthreads();
    if (lastsh != NB3_ - 1) return;
    __threadfence();

    // =============== HEAD (one block per batch) ===============
    if (b == 0) for (int i = B_ + B_ * FEAT_ + tid; i < osz; i += 512) dout[i] = 0.0f;

    float spw = psum * ip, slw = lsum * il;

    __syncthreads();   // guard big reuse
    // slot sums: one staged pass (16 slots, q sums 4 each)
    {
        float aA = 0.0f, aP = 0.0f, aC = 0.0f;
        #pragma unroll
        for (int s = 0; s < 4; s++) {
            int sl = q * 4 + s;
            aA += abarp_g[(size_t)(b * NB3_ + sl) * F_ + f];
            aP += Pwp_g[(size_t)(b * NB3_ + sl) * D_ + f];
            aC += Cwp_g[(size_t)(b * NB3_ + sl) * D_ + f];
        }
        big[q * 128 + f] = aA;
        big[512 + q * 128 + f] = aP;
        big[1024 + q * 128 + f] = aC;
    }
    __syncthreads();
    if (tid < 128) {
        absum[tid] = big[tid] + big[128+tid] + big[256+tid] + big[384+tid];
        Pws[tid]   = big[512+tid] + big[640+tid] + big[768+tid] + big[896+tid];
        Cws[tid]   = big[1024+tid] + big[1152+tid] + big[1280+tid] + big[1408+tid];
    }
    if (tid < K_) {
        float s = 0.0f;
        #pragma unroll
        for (int s2 = 0; s2 < NB1_; s2++) s += tstrp_g[(size_t)(b * NB1_ + s2) * 8 + tid];
        tst[tid] = s;
    }
    __syncthreads();
    if (tid < 128) {
        float fg = fg_mask[b * F_ + tid];
        float mexf = __expf(-(1.0f - fg) * 1e9f);
        la_s[tid] = absum[tid] * mexf * ip;
    }
    __syncthreads();

    // ligand pooling: 4 f-chunks x 128 d
    float ag = 0.0f, aL = 0.0f;
    #pragma unroll 8
    for (int i = 0; i < 32; i++) {
        int ff = q * 32 + i;
        float lv = ligand_emb[(size_t)(b * F_ + ff) * D_ + f];
        ag += la_s[ff] * lv;
        aL += lw_sm[ff] * lv;
    }
    big[q * 128 + f] = ag;
    big[512 + q * 128 + f] = aL;
    __syncthreads();
    if (tid < 128) {
        gs[tid] = big[tid] + big[128+tid] + big[256+tid] + big[384+tid];
        Ls[tid] = big[512+tid] + big[640+tid] + big[768+tid] + big[896+tid];
    }
    __syncthreads();

    // feat rows: warps 0-7 -> Wr/gs, warps 8-15 -> Wf/Cws; 4 rows per iteration
    {
        const float* Wm = (w < 8) ? Wr : Wf;
        const float* vec = (w < 8) ? gs : Cws;
        int rb = (w < 8) ? w * 16 : (w - 8) * 16;
        #pragma unroll 1
        for (int i = 0; i < 4; i++) {
            int r0 = rb + i * 4;
            float p0=0.f,p1=0.f,p2=0.f,p3=0.f;
            #pragma unroll
            for (int u = 0; u < 4; u++) {
                int j = t + 32 * u;
                float g = vec[j];
                p0 += Wm[(r0+0)*D_ + j] * g;
                p1 += Wm[(r0+1)*D_ + j] * g;
                p2 += Wm[(r0+2)*D_ + j] * g;
                p3 += Wm[(r0+3)*D_ + j] * g;
            }
            p0 = warpSum(p0); p1 = warpSum(p1); p2 = warpSum(p2); p3 = warpSum(p3);
            if (t == 0) {
                if (w < 8) {
                    feat[r0+0] = Pws[r0+0] + p0 + spw * br[r0+0];
                    feat[r0+1] = Pws[r0+1] + p1 + spw * br[r0+1];
                    feat[r0+2] = Pws[r0+2] + p2 + spw * br[r0+2];
                    feat[r0+3] = Pws[r0+3] + p3 + spw * br[r0+3];
                } else {
                    feat[128+r0+0] = Ls[r0+0] + p0 + slw * bf[r0+0];
                    feat[128+r0+1] = Ls[r0+1] + p1 + slw * bf[r0+1];
                    feat[128+r0+2] = Ls[r0+2] + p2 + slw * bf[r0+2];
                    feat[128+r0+3] = Ls[r0+3] + p3 + slw * bf[r0+3];
                }
            }
        }
    }
    if (tid < K_) feat[2 * D_ + tid] = tst[tid];
    __syncthreads();

    // norm + normalized-feat output
    float sv = (tid < FEAT_) ? feat[tid] * feat[tid] : 0.0f;
    float nrm = blockReduceSum(sv, red);
    float inv = 1.0f / fmaxf(sqrtf(nrm), 1e-12f);
    if (tid < FEAT_) {
        int oi = B_ + b * FEAT_ + tid;
        if (oi < osz) dout[oi] = feat[tid] * inv;
    }

    // MLP layer 1: 512 rows, 32 per warp, 4 per iteration
    {
        int rb = w * 32;
        #pragma unroll 1
        for (int i = 0; i < 8; i++) {
            int r0 = rb + i * 4;
            float p0=0.f,p1=0.f,p2=0.f,p3=0.f;
            #pragma unroll
            for (int u = 0; u < 8; u++) {
                int j = t + 32 * u;
                float fv = feat[j];
                p0 += W1[(r0+0)*FEAT_ + j] * fv;
                p1 += W1[(r0+1)*FEAT_ + j] * fv;
                p2 += W1[(r0+2)*FEAT_ + j] * fv;
                p3 += W1[(r0+3)*FEAT_ + j] * fv;
            }
            if (t < 7) {
                int j = 256 + t;
                float fv = feat[j];
                p0 += W1[(r0+0)*FEAT_ + j] * fv;
                p1 += W1[(r0+1)*FEAT_ + j] * fv;
                p2 += W1[(r0+2)*FEAT_ + j] * fv;
                p3 += W1[(r0+3)*FEAT_ + j] * fv;
            }
            p0 = warpSum(p0); p1 = warpSum(p1); p2 = warpSum(p2); p3 = warpSum(p3);
            if (t == 0) {
                h1[r0+0] = fmaxf(p0 + b1[r0+0], 0.0f);
                h1[r0+1] = fmaxf(p1 + b1[r0+1], 0.0f);
                h1[r0+2] = fmaxf(p2 + b1[r0+2], 0.0f);
                h1[r0+3] = fmaxf(p3 + b1[r0+3], 0.0f);
            }
        }
    }
    __syncthreads();

    // MLP layer 2: 256 rows, 16 per warp, 2 per iteration
    {
        int rb = w * 16;
        #pragma unroll 1
        for (int i = 0; i < 8; i++) {
            int r0 = rb + i * 2;
            float p0=0.f,p1=0.f;
            #pragma unroll
            for (int u = 0; u < 16; u++) {
                int j = t + 32 * u;
                float hv = h1[j];
                p0 += W2[(r0+0)*H_ + j] * hv;
                p1 += W2[(r0+1)*H_ + j] * hv;
            }
            p0 = warpSum(p0); p1 = warpSum(p1);
            if (t == 0) {
                h2[r0+0] = fmaxf(p0 + b2[r0+0], 0.0f);
                h2[r0+1] = fmaxf(p1 + b2[r0+1], 0.0f);
            }
        }
    }
    __syncthreads();
    float pv = (tid < H2_) ? W3[tid] * h2[tid] : 0.0f;
    float pred = blockReduceSum(pv, red);
    if (tid == 0 && b < osz) dout[b] = pred + b3[0];
}

// ---------------- launch ----------------
extern "C" void kernel_launch(void* const* d_in, const int* in_sizes, int n_in,
                              void* d_out, int out_size) {
    const float* lig    = (const float*)d_in[0];
    const float* prot   = (const float*)d_in[1];
    const float* logits = (const float*)d_in[2];
    const float* fg     = (const float*)d_in[3];
    const float* pmsk   = (const float*)d_in[4];
    const float* tw     = (const float*)d_in[5];
    const float* Wr = (const float*)d_in[6];  const float* br = (const float*)d_in[7];
    const float* Wf = (const float*)d_in[8];  const float* bf = (const float*)d_in[9];
    const float* W1 = (const float*)d_in[10]; const float* b1 = (const float*)d_in[11];
    const float* W2 = (const float*)d_in[12]; const float* b2 = (const float*)d_in[13];
    const float* W3 = (const float*)d_in[14]; const float* b3 = (const float*)d_in[15];
    float* out = (float*)d_out;

    k1_logits<<<dim3(NB1_, B_), 256>>>(logits, fg, pmsk, tw);
    k35<<<dim3(NB3_, B_), 512>>>(prot, lig, fg, pmsk, Wr, br, Wf, bf,
                                 W1, b1, W2, b2, W3, b3, out, out_size);
}

// round 6
// speedup vs baseline: 4.7353x; 1.1907x over previous
#include <cuda_runtime.h>
#include <math.h>

#define B_ 16
#define R_ 1024
#define F_ 128
#define D_ 128
#define K_ 7
#define H_ 512
#define H2_ 256
#define FEAT_ 263   // 2*D + K
#define NB1_ 32     // k1 blocks per batch (32 rows each)
#define NB3_ 32     // k3 blocks per batch (32 rows each)

// ---------------- device scratch (static, allocation-free) ----------------
__device__ float E_g[B_ * R_ * F_];          // exp(masked S)
__device__ float Zrow_g[B_ * R_];            // sum_f E*mexf
__device__ float pscore_g[B_ * R_];          // S.sum(f) * pm
__device__ float Zcolp_g[B_ * NB1_ * F_];    // partial: sum_r E*mexr
__device__ float ligcolp_g[B_ * NB1_ * F_];  // partial: sum_r S
__device__ float abarp_g[B_ * NB1_ * F_];    // partial: sum_r coef_r*E
__device__ float tstrp_g[B_ * NB1_ * 8];     // partial type strength
__device__ float Pwp_g[B_ * NB3_ * D_];      // partial: sum_r pscore_r*P  (unscaled)
__device__ float Cwp_g[B_ * NB3_ * D_];      // partial: sum_r craw_r*P    (unscaled)

// ---------------- helpers ----------------
__device__ __forceinline__ float warpSum(float v) {
    #pragma unroll
    for (int o = 16; o > 0; o >>= 1) v += __shfl_down_sync(0xffffffffu, v, o);
    return v;
}
__device__ __forceinline__ float warpAllSum(float v) {
    #pragma unroll
    for (int o = 16; o > 0; o >>= 1) v += __shfl_xor_sync(0xffffffffu, v, o);
    return v;
}
__device__ __forceinline__ float blockReduceSum(float v, float* sm) {
    int lane = threadIdx.x & 31, w = threadIdx.x >> 5;
    int nw = (blockDim.x + 31) >> 5;
    v = warpSum(v);
    if (lane == 0) sm[w] = v;
    __syncthreads();
    float r = (threadIdx.x < nw) ? sm[threadIdx.x] : 0.0f;
    if (w == 0) r = warpSum(r);
    if (threadIdx.x == 0) sm[0] = r;
    __syncthreads();
    r = sm[0];
    __syncthreads();
    return r;
}
__device__ __forceinline__ void l2pf(const void* p) {
    asm volatile("prefetch.global.L2 [%0];" :: "l"(p));
}

// ============ K1: logits pass — softmax-K, E, row stats, col+abar partials =
__global__ void __launch_bounds__(256, 4) k1_logits(const float* __restrict__ logits,
                          const float* __restrict__ fg_mask,
                          const float* __restrict__ prot_mask,
                          const float* __restrict__ tw) {
    int b = blockIdx.y, blk = blockIdx.x;
    int tid = threadIdx.x, w = tid >> 5, t = tid & 31;

    __shared__ float buf[8 * 896];     // 28KB: 8 logits rows / staging
    __shared__ float tks[8][8];
    __shared__ float wsh_s[8];

    if (tid < K_) {
        float x = tw[tid];
        wsh_s[tid] = fmaxf(x, 0.0f) + log1pf(expf(-fabsf(x)));
    }
    __syncthreads();
    float wshr[K_];
    #pragma unroll
    for (int k = 0; k < K_; k++) wshr[k] = wsh_s[k];

    float fgc[4], mexfc[4];
    #pragma unroll
    for (int c = 0; c < 4; c++) {
        fgc[c] = fg_mask[b * F_ + t + 32 * c];
        mexfc[c] = __expf(-(1.0f - fgc[c]) * 1e9f);
    }

    float zc[4] = {0,0,0,0}, lc[4] = {0,0,0,0}, ab[4] = {0,0,0,0};
    float tk[K_];
    #pragma unroll
    for (int k = 0; k < K_; k++) tk[k] = 0.0f;

    int r0 = blk * 32;
    for (int tile = 0; tile < 4; tile++) {
        const float4* src = (const float4*)(logits + (size_t)(b * R_ + r0 + tile * 8) * 896);
        __syncthreads();
        #pragma unroll
        for (int i = 0; i < 7; i++) ((float4*)buf)[tid + 256 * i] = src[tid + 256 * i];
        __syncthreads();

        int r = r0 + tile * 8 + w;
        float pm = prot_mask[b * R_ + r];
        float mexr = __expf(-(1.0f - pm) * 1e9f);
        float rowS = 0.0f, rowE = 0.0f;
        float Ev[4];

        #pragma unroll
        for (int c = 0; c < 4; c++) {
            int fb = w * 896 + (t + 32 * c) * 7;     // lane stride 7: conflict-free
            float x0 = buf[fb+0], x1 = buf[fb+1], x2 = buf[fb+2], x3 = buf[fb+3];
            float x4 = buf[fb+4], x5 = buf[fb+5], x6 = buf[fb+6];
            float m = fmaxf(fmaxf(fmaxf(x0,x1),fmaxf(x2,x3)),fmaxf(fmaxf(x4,x5),x6));
            float e0=__expf(x0-m), e1=__expf(x1-m), e2=__expf(x2-m), e3=__expf(x3-m);
            float e4=__expf(x4-m), e5=__expf(x5-m), e6=__expf(x6-m);
            float s = e0+e1+e2+e3+e4+e5+e6;
            float inv = __fdividef(1.0f, s);
            float w0=e0*inv*wshr[0], w1=e1*inv*wshr[1], w2=e2*inv*wshr[2], w3=e3*inv*wshr[3];
            float w4=e4*inv*wshr[4], w5=e5*inv*wshr[5], w6=e6*inv*wshr[6];
            tk[0]+=w0; tk[1]+=w1; tk[2]+=w2; tk[3]+=w3; tk[4]+=w4; tk[5]+=w5; tk[6]+=w6;
            float Sv = w0+w1+w2+w3+w4+w5+w6;
            float Sm = Sv * pm * fgc[c];
            float E = __expf(Sm);
            E_g[(size_t)(b * R_ + r) * F_ + t + 32 * c] = E;
            Ev[c] = E;
            rowS += Sm; rowE += E * mexfc[c];
            zc[c] += E * mexr; lc[c] += Sm;
        }
        rowS = warpAllSum(rowS);
        rowE = warpAllSum(rowE);
        float ps = rowS * pm;
        if (t == 0) { pscore_g[b * R_ + r] = ps; Zrow_g[b * R_ + r] = rowE; }
        float coef = __fdividef(ps, rowE);
        #pragma unroll
        for (int c = 0; c < 4; c++) ab[c] += coef * Ev[c];
    }

    #pragma unroll
    for (int k = 0; k < K_; k++) { float v = warpSum(tk[k]); if (t == 0) tks[w][k] = v; }
    __syncthreads();
    #pragma unroll
    for (int c = 0; c < 4; c++) {
        buf[w * 128 + t + 32 * c]        = zc[c];
        buf[1024 + w * 128 + t + 32 * c] = lc[c];
        buf[2048 + w * 128 + t + 32 * c] = ab[c];
    }
    __syncthreads();
    if (tid < 128) {
        float s = 0.0f, s2 = 0.0f, s3 = 0.0f;
        #pragma unroll
        for (int ww = 0; ww < 8; ww++) {
            s  += buf[ww * 128 + tid];
            s2 += buf[1024 + ww * 128 + tid];
            s3 += buf[2048 + ww * 128 + tid];
        }
        Zcolp_g[(size_t)(b * NB1_ + blk) * F_ + tid]   = s;
        ligcolp_g[(size_t)(b * NB1_ + blk) * F_ + tid] = s2;
        abarp_g[(size_t)(b * NB1_ + blk) * F_ + tid]   = s3;
    } else if (tid < 128 + K_) {
        int k = tid - 128;
        float s = 0.0f;
        #pragma unroll
        for (int ww = 0; ww < 8; ww++) s += tks[ww][k];
        tstrp_g[(size_t)(b * NB1_ + blk) * 8 + k] = s;
    }
}

// ============ K3: lean E pass — craw + unscaled Pw/Cw partials =============
__global__ void __launch_bounds__(256, 6) k3_epass(const float* __restrict__ protein_emb,
                        const float* __restrict__ ligand_emb,
                        const float* __restrict__ fg_mask,
                        const float* __restrict__ prot_mask,
                        const float* __restrict__ Wr, const float* __restrict__ Wf,
                        const float* __restrict__ W1, const float* __restrict__ W2) {
    int b = blockIdx.y, blk = blockIdx.x;
    int tid = threadIdx.x, w = tid >> 5, t = tid & 31;
    int f = tid & 127, q = tid >> 7;

    __shared__ float lco_sm[128];
    __shared__ float zsm[2][128], lsm[2][128];
    __shared__ float stage[2048];

    // L2 prefetch of head weights + ligand (covers all of them across 512 blocks)
    {
        int gb = b * NB3_ + blk;                       // 0..511
        long gid = (long)gb * 256 + tid;               // 0..131071
        const long n1 = 4208;                          // W1 lines
        const long n2 = 4096;                          // W2 lines
        const long nr = 512;                           // Wr/Wf lines each
        const long nl = 8192;                          // ligand lines (1MB)
        if (gid < n1)                      l2pf((const char*)W1 + gid * 128);
        else if (gid < n1+n2)              l2pf((const char*)W2 + (gid-n1) * 128);
        else if (gid < n1+n2+nr)           l2pf((const char*)Wr + (gid-n1-n2) * 128);
        else if (gid < n1+n2+2*nr)         l2pf((const char*)Wf + (gid-n1-n2-nr) * 128);
        else if (gid < n1+n2+2*nr+nl)      l2pf((const char*)ligand_emb + (gid-n1-n2-2*nr) * 128);
    }

    // lcoef from k1 column partials (no global reductions needed)
    float zs = 0.0f, ls = 0.0f;
    for (int s = q * 16; s < q * 16 + 16; s++) {
        zs += Zcolp_g[(size_t)(b * NB1_ + s) * F_ + f];
        ls += ligcolp_g[(size_t)(b * NB1_ + s) * F_ + f];
    }
    zsm[q][f] = zs; lsm[q][f] = ls;
    __syncthreads();
    if (tid < 128) {
        float Zc  = zsm[0][tid] + zsm[1][tid];
        float lgc = lsm[0][tid] + lsm[1][tid];
        lco_sm[tid] = __fdividef(lgc * fg_mask[b * F_ + tid], Zc);
    }
    __syncthreads();
    float lcoc[4];
    #pragma unroll
    for (int c = 0; c < 4; c++) lcoc[c] = lco_sm[t + 32 * c];

    // row loop: 8 warps x 4 rows
    float Pa[4] = {0,0,0,0}, Ca[4] = {0,0,0,0};
    int rbase = blk * 32 + w * 4;
    #pragma unroll
    for (int i = 0; i < 4; i++) {
        int r = rbase + i;
        float ps = pscore_g[b * R_ + r];
        float pm = prot_mask[b * R_ + r];
        float mexr = __expf(-(1.0f - pm) * 1e9f);
        float E[4], dv = 0.0f;
        #pragma unroll
        for (int c = 0; c < 4; c++) {
            E[c] = E_g[(size_t)(b * R_ + r) * F_ + t + 32 * c];
            dv += lcoc[c] * E[c];
        }
        float craw = mexr * warpAllSum(dv);
        #pragma unroll
        for (int c = 0; c < 4; c++) {
            float Pv = protein_emb[(size_t)(b * R_ + r) * D_ + t + 32 * c];
            Pa[c] += ps * Pv;
            Ca[c] += craw * Pv;
        }
    }

    __syncthreads();
    #pragma unroll
    for (int c = 0; c < 4; c++) {
        stage[w * 128 + t + 32 * c]        = Pa[c];
        stage[1024 + w * 128 + t + 32 * c] = Ca[c];
    }
    __syncthreads();
    if (tid < 128) {
        float s = 0.0f;
        #pragma unroll
        for (int ww = 0; ww < 8; ww++) s += stage[ww * 128 + tid];
        Pwp_g[(size_t)(b * NB3_ + blk) * D_ + tid] = s;
    } else {
        float s = 0.0f;
        #pragma unroll
        for (int ww = 0; ww < 8; ww++) s += stage[1024 + ww * 128 + f];
        Cwp_g[(size_t)(b * NB3_ + blk) * D_ + f] = s;
    }
}

// ============ KHEAD: pools + feat + norm + MLP (one block per batch) =======
__global__ void __launch_bounds__(512, 2) khead(const float* __restrict__ ligand_emb,
                        const float* __restrict__ fg_mask,
                        const float* __restrict__ Wr, const float* __restrict__ br,
                        const float* __restrict__ Wf, const float* __restrict__ bf,
                        const float* __restrict__ W1, const float* __restrict__ b1,
                        const float* __restrict__ W2, const float* __restrict__ b2,
                        const float* __restrict__ W3, const float* __restrict__ b3,
                        float* __restrict__ dout, int osz) {
    int b = blockIdx.x, tid = threadIdx.x, w = tid >> 5, t = tid & 31;
    int f = tid & 127, q = tid >> 7;

    __shared__ float red[32];
    __shared__ float big[2048];
    __shared__ float lw_sm[128], la_s[128];
    __shared__ float absum[128], Pws[128], Cws[128];
    __shared__ float gs[128], Ls[128];
    __shared__ float feat[FEAT_ + 1];
    __shared__ float h1[H_], h2[H2_];
    __shared__ float tst[8];

    if (b == 0) for (int i = B_ + B_ * FEAT_ + tid; i < osz; i += 512) dout[i] = 0.0f;

    // psum
    float v = pscore_g[b * R_ + tid] + pscore_g[b * R_ + 512 + tid];
    float psum = blockReduceSum(v, red);
    float ip = __fdividef(1.0f, psum + 1e-8f);
    float spw = psum * ip;

    // ligcol sums -> lsum, lw
    {
        float ls = 0.0f;
        for (int s = q * 8; s < q * 8 + 8; s++) ls += ligcolp_g[(size_t)(b * NB1_ + s) * F_ + f];
        big[q * 128 + f] = ls;
    }
    __syncthreads();
    float lw0 = 0.0f;
    if (tid < 128) {
        float lgc = big[tid] + big[128+tid] + big[256+tid] + big[384+tid];
        lw0 = lgc * fg_mask[b * F_ + tid];
    }
    float lsum = blockReduceSum(lw0, red);
    float il = __fdividef(1.0f, lsum + 1e-8f);
    float slw = lsum * il;
    if (tid < 128) lw_sm[tid] = lw0 * il;

    // slot sums: abar (NB1 slots), Pw/Cw (NB3 slots)
    {
        float aA = 0.0f, aP = 0.0f, aC = 0.0f;
        #pragma unroll
        for (int s = 0; s < 8; s++) {
            int s1 = q * 8 + s;
            aA += abarp_g[(size_t)(b * NB1_ + s1) * F_ + f];
            aP += Pwp_g[(size_t)(b * NB3_ + s1) * D_ + f];
            aC += Cwp_g[(size_t)(b * NB3_ + s1) * D_ + f];
        }
        big[512 + q * 128 + f]  = aA;
        big[1024 + q * 128 + f] = aP;
        big[1536 + q * 128 + f] = aC;
    }
    __syncthreads();
    if (tid < 128) {
        float aA = big[512+tid] + big[640+tid] + big[768+tid] + big[896+tid];
        float aP = big[1024+tid] + big[1152+tid] + big[1280+tid] + big[1408+tid];
        float aC = big[1536+tid] + big[1664+tid] + big[1792+tid] + big[1920+tid];
        float fg = fg_mask[b * F_ + tid];
        float mexf = __expf(-(1.0f - fg) * 1e9f);
        la_s[tid] = aA * mexf * ip;
        Pws[tid] = aP * ip;
        Cws[tid] = aC * il;
    }
    if (tid < K_) {
        float s = 0.0f;
        #pragma unroll
        for (int s2 = 0; s2 < NB1_; s2++) s += tstrp_g[(size_t)(b * NB1_ + s2) * 8 + tid];
        tst[tid] = s;
    }
    __syncthreads();

    // ligand pooling: 4 f-chunks x 128 d
    float ag = 0.0f, aL = 0.0f;
    #pragma unroll 8
    for (int i = 0; i < 32; i++) {
        int ff = q * 32 + i;
        float lv = ligand_emb[(size_t)(b * F_ + ff) * D_ + f];
        ag += la_s[ff] * lv;
        aL += lw_sm[ff] * lv;
    }
    big[q * 128 + f] = ag;
    big[512 + q * 128 + f] = aL;
    __syncthreads();
    if (tid < 128) {
        gs[tid] = big[tid] + big[128+tid] + big[256+tid] + big[384+tid];
        Ls[tid] = big[512+tid] + big[640+tid] + big[768+tid] + big[896+tid];
    }
    __syncthreads();

    // feat rows: warps 0-7 -> Wr/gs, 8-15 -> Wf/Cws; 4 rows per iteration
    {
        const float* Wm = (w < 8) ? Wr : Wf;
        const float* vec = (w < 8) ? gs : Cws;
        int rb = (w & 7) * 16;
        #pragma unroll 1
        for (int i = 0; i < 4; i++) {
            int r0 = rb + i * 4;
            float p0=0.f,p1=0.f,p2=0.f,p3=0.f;
            #pragma unroll
            for (int u = 0; u < 4; u++) {
                int j = t + 32 * u;
                float g = vec[j];
                p0 += Wm[(r0+0)*D_ + j] * g;
                p1 += Wm[(r0+1)*D_ + j] * g;
                p2 += Wm[(r0+2)*D_ + j] * g;
                p3 += Wm[(r0+3)*D_ + j] * g;
            }
            p0 = warpSum(p0); p1 = warpSum(p1); p2 = warpSum(p2); p3 = warpSum(p3);
            if (t == 0) {
                if (w < 8) {
                    feat[r0+0] = Pws[r0+0] + p0 + spw * br[r0+0];
                    feat[r0+1] = Pws[r0+1] + p1 + spw * br[r0+1];
                    feat[r0+2] = Pws[r0+2] + p2 + spw * br[r0+2];
                    feat[r0+3] = Pws[r0+3] + p3 + spw * br[r0+3];
                } else {
                    feat[128+r0+0] = Ls[r0+0] + p0 + slw * bf[r0+0];
                    feat[128+r0+1] = Ls[r0+1] + p1 + slw * bf[r0+1];
                    feat[128+r0+2] = Ls[r0+2] + p2 + slw * bf[r0+2];
                    feat[128+r0+3] = Ls[r0+3] + p3 + slw * bf[r0+3];
                }
            }
        }
    }
    if (tid < K_) feat[2 * D_ + tid] = tst[tid];
    __syncthreads();

    // norm + normalized-feat output
    float sv = (tid < FEAT_) ? feat[tid] * feat[tid] : 0.0f;
    float nrm = blockReduceSum(sv, red);
    float inv = 1.0f / fmaxf(sqrtf(nrm), 1e-12f);
    if (tid < FEAT_) {
        int oi = B_ + b * FEAT_ + tid;
        if (oi < osz) dout[oi] = feat[tid] * inv;
    }

    // MLP layer 1: 512 rows, 32/warp, 4 per iteration
    {
        int rb = w * 32;
        #pragma unroll 1
        for (int i = 0; i < 8; i++) {
            int r0 = rb + i * 4;
            float p0=0.f,p1=0.f,p2=0.f,p3=0.f;
            #pragma unroll
            for (int u = 0; u < 8; u++) {
                int j = t + 32 * u;
                float fv = feat[j];
                p0 += W1[(r0+0)*FEAT_ + j] * fv;
                p1 += W1[(r0+1)*FEAT_ + j] * fv;
                p2 += W1[(r0+2)*FEAT_ + j] * fv;
                p3 += W1[(r0+3)*FEAT_ + j] * fv;
            }
            if (t < 7) {
                int j = 256 + t;
                float fv = feat[j];
                p0 += W1[(r0+0)*FEAT_ + j] * fv;
                p1 += W1[(r0+1)*FEAT_ + j] * fv;
                p2 += W1[(r0+2)*FEAT_ + j] * fv;
                p3 += W1[(r0+3)*FEAT_ + j] * fv;
            }
            p0 = warpSum(p0); p1 = warpSum(p1); p2 = warpSum(p2); p3 = warpSum(p3);
            if (t == 0) {
                h1[r0+0] = fmaxf(p0 + b1[r0+0], 0.0f);
                h1[r0+1] = fmaxf(p1 + b1[r0+1], 0.0f);
                h1[r0+2] = fmaxf(p2 + b1[r0+2], 0.0f);
                h1[r0+3] = fmaxf(p3 + b1[r0+3], 0.0f);
            }
        }
    }
    __syncthreads();

    // MLP layer 2: 256 rows, 16/warp, 2 per iteration
    {
        int rb = w * 16;
        #pragma unroll 1
        for (int i = 0; i < 8; i++) {
            int r0 = rb + i * 2;
            float p0=0.f,p1=0.f;
            #pragma unroll
            for (int u = 0; u < 16; u++) {
                int j = t + 32 * u;
                float hv = h1[j];
                p0 += W2[(r0+0)*H_ + j] * hv;
                p1 += W2[(r0+1)*H_ + j] * hv;
            }
            p0 = warpSum(p0); p1 = warpSum(p1);
            if (t == 0) {
                h2[r0+0] = fmaxf(p0 + b2[r0+0], 0.0f);
                h2[r0+1] = fmaxf(p1 + b2[r0+1], 0.0f);
            }
        }
    }
    __syncthreads();
    float pv = (tid < H2_) ? W3[tid] * h2[tid] : 0.0f;
    float pred = blockReduceSum(pv, red);
    if (tid == 0 && b < osz) dout[b] = pred + b3[0];
}

// ---------------- launch ----------------
extern "C" void kernel_launch(void* const* d_in, const int* in_sizes, int n_in,
                              void* d_out, int out_size) {
    const float* lig    = (const float*)d_in[0];
    const float* prot   = (const float*)d_in[1];
    const float* logits = (const float*)d_in[2];
    const float* fg     = (const float*)d_in[3];
    const float* pmsk   = (const float*)d_in[4];
    const float* tw     = (const float*)d_in[5];
    const float* Wr = (const float*)d_in[6];  const float* br = (const float*)d_in[7];
    const float* Wf = (const float*)d_in[8];  const float* bf = (const float*)d_in[9];
    const float* W1 = (const float*)d_in[10]; const float* b1 = (const float*)d_in[11];
    const float* W2 = (const float*)d_in[12]; const float* b2 = (const float*)d_in[13];
    const float* W3 = (const float*)d_in[14]; const float* b3 = (const float*)d_in[15];
    float* out = (float*)d_out;

    k1_logits<<<dim3(NB1_, B_), 256>>>(logits, fg, pmsk, tw);
    k3_epass<<<dim3(NB3_, B_), 256>>>(prot, lig, fg, pmsk, Wr, Wf, W1, W2);
    khead<<<B_, 512>>>(lig, fg, Wr, br, Wf, bf, W1, b1, W2, b2, W3, b3, out, out_size);
}